// round 13
// baseline (speedup 1.0000x reference)
#include <cuda_runtime.h>
#include <cuda_bf16.h>
#include <math.h>
#include <stdint.h>

// ---------------- problem constants (fixed shapes) ----------------
#define B_   8
#define T_   1024
#define C_   768
#define H_   12
#define HS_  64
#define PH_  32
#define PW_  32
#define NR_  (B_ * T_)          // 8192 rows
#define NC_  ((size_t)NR_ * C_) // 6291456 elems
#define WSZ_ ((size_t)C_ * C_)  // 589824

// ---------------- scratch ----------------
__device__ __align__(16) float g_scratch[10 * NC_ + (size_t)NR_ * 160 + (size_t)NR_ * 64 + (size_t)NR_ * H_];
__device__ __align__(16) __nv_bfloat16 g_acthi[4 * NC_];   // slots: 0=k,1=v,2=r,3=g
__device__ __align__(16) __nv_bfloat16 g_actlo[4 * NC_];
__device__ __align__(16) __nv_bfloat16 g_w5hi[5 * WSZ_];   // W_r,W_k,W_v,W_g,W_o
__device__ __align__(16) __nv_bfloat16 g_w5lo[5 * WSZ_];

#define OFF_XX   ((size_t)0)
#define OFF_XXX  (OFF_XX  + NC_)
#define OFF_T5   (OFF_XXX + NC_)
#define OFF_XW   (OFF_T5  + (size_t)NR_ * 160)
#define OFF_R    (OFF_XW  + NC_)      // R,K,V,G contiguous (4*NC_) for batched GEMM
#define OFF_K    (OFF_R   + NC_)
#define OFF_V    (OFF_K   + NC_)
#define OFF_G    (OFF_V   + NC_)
#define OFF_H1   (OFF_G   + NC_)
#define OFF_WDEC (OFF_H1  + (size_t)NR_ * 64)
#define OFF_Y    (OFF_WDEC+ NC_)

// ========================= helpers ==========================
__device__ __forceinline__ uint32_t smem_u32(const void* p) {
    uint32_t a;
    asm("{ .reg .u64 t; cvta.to.shared.u64 t, %1; cvt.u32.u64 %0, t; }" : "=r"(a) : "l"(p));
    return a;
}
__device__ __forceinline__ void ldsm_x4(uint32_t* r, uint32_t addr) {
    asm volatile("ldmatrix.sync.aligned.m8n8.x4.shared.b16 {%0,%1,%2,%3}, [%4];"
                 : "=r"(r[0]), "=r"(r[1]), "=r"(r[2]), "=r"(r[3]) : "r"(addr));
}
__device__ __forceinline__ void mma_bf16(float* c, const uint32_t* a, uint32_t b0, uint32_t b1) {
    asm volatile("mma.sync.aligned.m16n8k16.row.col.f32.bf16.bf16.f32 "
                 "{%0,%1,%2,%3}, {%4,%5,%6,%7}, {%8,%9}, {%0,%1,%2,%3};"
                 : "+f"(c[0]), "+f"(c[1]), "+f"(c[2]), "+f"(c[3])
                 : "r"(a[0]), "r"(a[1]), "r"(a[2]), "r"(a[3]), "r"(b0), "r"(b1));
}

// ==========================================================================
// bf16-split tensor-core GEMM body (device inline, used by both launchers)
// ==========================================================================
#define PLANE_   2080
#define ATILE_   (4 * PLANE_)
#define BUFSZ_   (2 * ATILE_)

__device__ __forceinline__ void gemm_mma_body(
    const __nv_bfloat16* __restrict__ Ahi, const __nv_bfloat16* __restrict__ Alo,
    const __nv_bfloat16* __restrict__ Whi, const __nv_bfloat16* __restrict__ Wlo,
    float* __restrict__ Cmat, int doRelu, char* sm)
{
    const int tid  = threadIdx.x;
    const int warp = tid >> 5;
    const int lane = tid & 31;
    const int m0 = blockIdx.y * 128;
    const int n0 = blockIdx.x * 128;
    const int wm = warp >> 2;
    const int wn = warp & 3;

    float acc[4][4][4];
#pragma unroll
    for (int i = 0; i < 4; i++)
#pragma unroll
        for (int j = 0; j < 4; j++)
#pragma unroll
            for (int q = 0; q < 4; q++) acc[i][j][q] = 0.f;

    const int ldrow = tid >> 1;
    const int ldcb  = (tid & 1) * 2;

    uint4 ra[2], rb[2];

    const uint32_t sb = smem_u32(sm);
    const int lgrp = lane >> 3;
    const int lrl  = lane & 7;

#define LDG_T(c_)                                                               \
    {                                                                           \
        const int seg_ = (c_) / 24;                                             \
        const int kc_  = ((c_) % 24) * 32;                                      \
        const __nv_bfloat16* Ag = (seg_ == 1) ? Alo : Ahi;                      \
        const __nv_bfloat16* Bg = (seg_ == 2) ? Wlo : Whi;                      \
        const __nv_bfloat16* ap = Ag + (size_t)(m0 + ldrow) * C_ + kc_ + ldcb * 8; \
        const __nv_bfloat16* bp = Bg + (size_t)(n0 + ldrow) * C_ + kc_ + ldcb * 8; \
        ra[0] = *(const uint4*)ap; ra[1] = *(const uint4*)(ap + 8);             \
        rb[0] = *(const uint4*)bp; rb[1] = *(const uint4*)(bp + 8);             \
    }

#define STS_T(buf_)                                                             \
    {                                                                           \
        char* b_ = sm + (buf_) * BUFSZ_;                                        \
        *(uint4*)(b_ + (ldcb + 0) * PLANE_ + ldrow * 16) = ra[0];               \
        *(uint4*)(b_ + (ldcb + 1) * PLANE_ + ldrow * 16) = ra[1];               \
        *(uint4*)(b_ + ATILE_ + (ldcb + 0) * PLANE_ + ldrow * 16) = rb[0];      \
        *(uint4*)(b_ + ATILE_ + (ldcb + 1) * PLANE_ + ldrow * 16) = rb[1];      \
    }

    LDG_T(0);
    STS_T(0);
    __syncthreads();

    for (int c = 0; c < 72; c++) {
        const int buf = c & 1;
        const bool hasNext = (c + 1 < 72);
        if (hasNext) LDG_T(c + 1);

        const uint32_t abase = sb + buf * BUFSZ_;
        const uint32_t bbase = abase + ATILE_;

#pragma unroll
        for (int kk = 0; kk < 2; kk++) {
            uint32_t afr[4][4], bfr[2][4];
#pragma unroll
            for (int mt = 0; mt < 4; mt++) {
                int row   = wm * 64 + mt * 16 + (lgrp & 1) * 8 + lrl;
                int chunk = kk * 2 + (lgrp >> 1);
                ldsm_x4(afr[mt], abase + chunk * PLANE_ + row * 16);
            }
#pragma unroll
            for (int nt = 0; nt < 2; nt++) {
                int nr    = wn * 32 + nt * 16 + (lgrp >> 1) * 8 + lrl;
                int chunk = kk * 2 + (lgrp & 1);
                ldsm_x4(bfr[nt], bbase + chunk * PLANE_ + nr * 16);
            }
#pragma unroll
            for (int mt = 0; mt < 4; mt++)
#pragma unroll
                for (int ng = 0; ng < 4; ng++)
                    mma_bf16(acc[mt][ng], afr[mt], bfr[ng >> 1][(ng & 1) * 2 + 0],
                             bfr[ng >> 1][(ng & 1) * 2 + 1]);
        }

        if (hasNext) {
            STS_T(buf ^ 1);
            __syncthreads();
        }
    }
#undef LDG_T
#undef STS_T

#pragma unroll
    for (int mt = 0; mt < 4; mt++) {
        const int r0 = m0 + wm * 64 + mt * 16 + (lane >> 2);
#pragma unroll
        for (int ng = 0; ng < 4; ng++) {
            const int col = n0 + wn * 32 + ng * 8 + (lane & 3) * 2;
            float c0 = acc[mt][ng][0], c1 = acc[mt][ng][1];
            float c2 = acc[mt][ng][2], c3 = acc[mt][ng][3];
            if (doRelu) {
                c0 = fmaxf(c0, 0.f); c1 = fmaxf(c1, 0.f);
                c2 = fmaxf(c2, 0.f); c3 = fmaxf(c3, 0.f);
            }
            *(float2*)(Cmat + (size_t)r0 * C_ + col)       = make_float2(c0, c1);
            *(float2*)(Cmat + (size_t)(r0 + 8) * C_ + col) = make_float2(c2, c3);
        }
    }
}

// Batched r/k/v/g GEMMs: gridDim.z = 4 selects act slot / weight / output.
__global__ void __launch_bounds__(256, 2)
k_gemm_mma4(const __nv_bfloat16* __restrict__ acthi, const __nv_bfloat16* __restrict__ actlo,
            const __nv_bfloat16* __restrict__ w5hi, const __nv_bfloat16* __restrict__ w5lo,
            float* __restrict__ outbase)
{
    __shared__ __align__(16) char sm[2 * BUFSZ_];
    const int z = blockIdx.z;
    const int aslot = (z == 0) ? 2 : (z == 1) ? 0 : (z == 2) ? 1 : 3;
    gemm_mma_body(acthi + (size_t)aslot * NC_, actlo + (size_t)aslot * NC_,
                  w5hi + (size_t)z * WSZ_, w5lo + (size_t)z * WSZ_,
                  outbase + (size_t)z * NC_, z == 3, sm);
}

// Single GEMM (W_o path)
__global__ void __launch_bounds__(256, 2)
k_gemm_mma(const __nv_bfloat16* __restrict__ Ahi, const __nv_bfloat16* __restrict__ Alo,
           const __nv_bfloat16* __restrict__ Whi, const __nv_bfloat16* __restrict__ Wlo,
           float* __restrict__ Cmat, int doRelu)
{
    __shared__ __align__(16) char sm[2 * BUFSZ_];
    gemm_mma_body(Ahi, Alo, Whi, Wlo, Cmat, doRelu, sm);
}

// ==========================================================================
// Split all five weight matrices into bf16 hi/lo once (float4 vectorized).
// ==========================================================================
__global__ void __launch_bounds__(256)
k_split5(const float* __restrict__ w0, const float* __restrict__ w1,
         const float* __restrict__ w2, const float* __restrict__ w3,
         const float* __restrict__ w4,
         __nv_bfloat16* __restrict__ hi, __nv_bfloat16* __restrict__ lo)
{
    size_t i4 = (size_t)blockIdx.x * blockDim.x + threadIdx.x;
    size_t idx = i4 * 4;
    int sel = (int)(idx / WSZ_);
    size_t off = idx % WSZ_;
    const float* src = (sel == 0) ? w0 : (sel == 1) ? w1 : (sel == 2) ? w2 : (sel == 3) ? w3 : w4;
    float4 a = *(const float4*)(src + off);
    __nv_bfloat16 h0 = __float2bfloat16(a.x);
    __nv_bfloat16 h1 = __float2bfloat16(a.y);
    __nv_bfloat16 h2 = __float2bfloat16(a.z);
    __nv_bfloat16 h3 = __float2bfloat16(a.w);
    __nv_bfloat162 hp0, hp1, lp0, lp1;
    hp0.x = h0; hp0.y = h1; hp1.x = h2; hp1.y = h3;
    lp0.x = __float2bfloat16(a.x - __bfloat162float(h0));
    lp0.y = __float2bfloat16(a.y - __bfloat162float(h1));
    lp1.x = __float2bfloat16(a.z - __bfloat162float(h2));
    lp1.y = __float2bfloat16(a.w - __bfloat162float(h3));
    *(uint2*)(hi + idx) = make_uint2(*(uint32_t*)&hp0, *(uint32_t*)&hp1);
    *(uint2*)(lo + idx) = make_uint2(*(uint32_t*)&lp0, *(uint32_t*)&lp1);
}

// ==========================================================================
// Kernel 1: q-shift (float4) -> xx = shift(x) - x ; xxx = x + xx * maa_x
// ==========================================================================
__global__ void __launch_bounds__(256)
k_shift(const float* __restrict__ x, const float* __restrict__ maa_x,
        float* __restrict__ xx, float* __restrict__ xxx)
{
    size_t i4 = (size_t)blockIdx.x * blockDim.x + threadIdx.x;
    size_t idx = i4 * 4;
    int c  = (int)(idx % C_);
    int bt = (int)(idx / C_);
    int t  = bt % T_;
    int w  = t % PW_;
    int h  = t / PW_;
    int quarter = (c & (HS_ - 1)) >> 4;

    float4 src = make_float4(0.f, 0.f, 0.f, 0.f);
    if (quarter == 0)      { if (w > 0)       src = *(const float4*)(x + idx - C_); }
    else if (quarter == 1) { if (w < PW_ - 1) src = *(const float4*)(x + idx + C_); }
    else if (quarter == 2) { if (h > 0)       src = *(const float4*)(x + idx - PW_ * C_); }
    else                   { if (h < PH_ - 1) src = *(const float4*)(x + idx + PW_ * C_); }

    float4 xv = *(const float4*)(x + idx);
    float4 mv = *(const float4*)(maa_x + c);
    float4 d, o;
    d.x = src.x - xv.x; d.y = src.y - xv.y; d.z = src.z - xv.z; d.w = src.w - xv.w;
    o.x = fmaf(d.x, mv.x, xv.x); o.y = fmaf(d.y, mv.y, xv.y);
    o.z = fmaf(d.z, mv.z, xv.z); o.w = fmaf(d.w, mv.w, xv.w);
    *(float4*)(xx + idx)  = d;
    *(float4*)(xxx + idx) = o;
}

// ==========================================================================
// Pipelined tiled fp32 GEMM (small N/K GEMMs only)
// ==========================================================================
template<int EPI, bool BNT>
__global__ void __launch_bounds__(256, 2)
k_gemm(const float* __restrict__ A, const float* __restrict__ B,
       float* __restrict__ Cmat, int M, int N, int K, const float* __restrict__ bias)
{
    __shared__ float As[2][16][132];
    __shared__ float Bs[2][16][132];

    const int m0   = blockIdx.y * 128;
    const int n0   = blockIdx.x * 128;
    const int tid  = threadIdx.x;
    const int warp = tid >> 5;
    const int lane = tid & 31;
    const int tm   = (warp >> 2) * 64 + (lane >> 2) * 8;
    const int tn   = (warp & 3) * 32 + (lane & 3) * 8;

    float acc[8][8];
#pragma unroll
    for (int i = 0; i < 8; i++)
#pragma unroll
        for (int j = 0; j < 8; j++) acc[i][j] = 0.f;

    float4 aR[2], bR[2];

#define LDG_TILE(k0_)                                                          \
    {                                                                          \
        _Pragma("unroll")                                                      \
        for (int l = 0; l < 2; l++) {                                          \
            int e  = tid + l * 256;                                            \
            int am = e >> 2;                                                   \
            int ak = (e & 3) * 4;                                              \
            aR[l] = *(const float4*)(A + (size_t)(m0 + am) * K + (k0_) + ak);  \
            if (BNT) {                                                         \
                int bn = e >> 2;                                               \
                int bk = (e & 3) * 4;                                          \
                bR[l] = make_float4(0.f, 0.f, 0.f, 0.f);                       \
                if (n0 + bn < N)                                               \
                    bR[l] = *(const float4*)(B + (size_t)(n0 + bn) * K + (k0_) + bk); \
            } else {                                                           \
                int bk = e >> 5;                                               \
                int bn = (e & 31) * 4;                                         \
                bR[l] = make_float4(0.f, 0.f, 0.f, 0.f);                       \
                if (n0 + bn < N)                                               \
                    bR[l] = *(const float4*)(B + (size_t)((k0_) + bk) * N + n0 + bn); \
            }                                                                  \
        }                                                                      \
    }

#define STS_TILE(buf_)                                                         \
    {                                                                          \
        _Pragma("unroll")                                                      \
        for (int l = 0; l < 2; l++) {                                          \
            int e  = tid + l * 256;                                            \
            int am = e >> 2;                                                   \
            int ak = (e & 3) * 4;                                              \
            As[buf_][ak + 0][am] = aR[l].x; As[buf_][ak + 1][am] = aR[l].y;    \
            As[buf_][ak + 2][am] = aR[l].z; As[buf_][ak + 3][am] = aR[l].w;    \
            if (BNT) {                                                         \
                int bn = e >> 2;                                               \
                int bk = (e & 3) * 4;                                          \
                Bs[buf_][bk + 0][bn] = bR[l].x; Bs[buf_][bk + 1][bn] = bR[l].y;\
                Bs[buf_][bk + 2][bn] = bR[l].z; Bs[buf_][bk + 3][bn] = bR[l].w;\
            } else {                                                           \
                int bk = e >> 5;                                               \
                int bn = (e & 31) * 4;                                         \
                *(float4*)(&Bs[buf_][bk][bn]) = bR[l];                         \
            }                                                                  \
        }                                                                      \
    }

    LDG_TILE(0);
    STS_TILE(0);
    __syncthreads();

    int buf = 0;
    for (int k0 = 0; k0 < K; k0 += 16) {
        const bool hasNext = (k0 + 16 < K);
        if (hasNext) LDG_TILE(k0 + 16);

#pragma unroll
        for (int kk = 0; kk < 16; kk++) {
            float a[8], b[8];
            *(float4*)(a)     = *(const float4*)(&As[buf][kk][tm]);
            *(float4*)(a + 4) = *(const float4*)(&As[buf][kk][tm + 4]);
            *(float4*)(b)     = *(const float4*)(&Bs[buf][kk][tn]);
            *(float4*)(b + 4) = *(const float4*)(&Bs[buf][kk][tn + 4]);
#pragma unroll
            for (int i = 0; i < 8; i++)
#pragma unroll
                for (int j = 0; j < 8; j++)
                    acc[i][j] = fmaf(a[i], b[j], acc[i][j]);
        }

        if (hasNext) {
            STS_TILE(buf ^ 1);
            __syncthreads();
            buf ^= 1;
        }
    }
#undef LDG_TILE
#undef STS_TILE

#pragma unroll
    for (int i = 0; i < 8; i++) {
        int m = m0 + tm + i;
#pragma unroll
        for (int j = 0; j < 8; j++) {
            int n = n0 + tn + j;
            if (n < N) {
                float v = acc[i][j];
                if (EPI == 1) v = tanhf(v);
                else if (EPI == 2) v = fmaxf(v, 0.f);
                else if (EPI == 3) v = expf(-expf(bias[n] + v));
                Cmat[(size_t)m * N + n] = v;
            }
        }
    }
}

// ==========================================================================
// Fused token-mix v4 (R10/R11 winner, unchanged)
// ==========================================================================
__global__ void __launch_bounds__(256, 2)
k_mix(const float* __restrict__ x, const float* __restrict__ xx,
      const float* __restrict__ t5, const float* __restrict__ w2,
      const float* __restrict__ ma0, const float* __restrict__ ma1,
      const float* __restrict__ ma2, const float* __restrict__ ma3,
      const float* __restrict__ ma4,
      float* __restrict__ xw,
      __nv_bfloat16* __restrict__ acthi, __nv_bfloat16* __restrict__ actlo)
{
    const int r0  = blockIdx.x * 64;
    const int c0  = blockIdx.y * 128;
    const int tid = threadIdx.x;
    const int cp  = (tid & 63) * 2;
    const int rh  = tid >> 6;

    __shared__ __align__(16) float tsh[64][36];

    float2 mfv[5];
    mfv[0] = *(const float2*)(ma0 + c0 + cp);
    mfv[1] = *(const float2*)(ma1 + c0 + cp);
    mfv[2] = *(const float2*)(ma2 + c0 + cp);
    mfv[3] = *(const float2*)(ma3 + c0 + cp);
    mfv[4] = *(const float2*)(ma4 + c0 + cp);

    for (int f = 0; f < 5; f++) {
#pragma unroll
        for (int l = 0; l < 8; l++) {
            int e = tid + l * 256;
            tsh[e >> 5][e & 31] = t5[(size_t)(r0 + (e >> 5)) * 160 + f * 32 + (e & 31)];
        }
        float2 wreg[32];
#pragma unroll
        for (int rr = 0; rr < 32; rr++)
            wreg[rr] = *(const float2*)(w2 + (size_t)(f * 32 + rr) * C_ + c0 + cp);
        __syncthreads();

        const float2 mf = mfv[f];
        const size_t slotoff = (size_t)(f - 1) * NC_;
        size_t idx = (size_t)(r0 + rh) * C_ + c0 + cp;

#pragma unroll 4
        for (int it = 0; it < 16; it++) {
            const int row = rh + it * 4;
            float2 xv  = *(const float2*)(x + idx);
            float2 xxv = *(const float2*)(xx + idx);
            const float4* trow = (const float4*)(&tsh[row][0]);
            float a0 = 0.f, a1 = 0.f;
#pragma unroll
            for (int q = 0; q < 8; q++) {
                float4 t4 = trow[q];
                float2 w0 = wreg[4 * q + 0], w1 = wreg[4 * q + 1];
                float2 w2r = wreg[4 * q + 2], w3 = wreg[4 * q + 3];
                a0 = fmaf(t4.x, w0.x, a0); a1 = fmaf(t4.x, w0.y, a1);
                a0 = fmaf(t4.y, w1.x, a0); a1 = fmaf(t4.y, w1.y, a1);
                a0 = fmaf(t4.z, w2r.x, a0); a1 = fmaf(t4.z, w2r.y, a1);
                a0 = fmaf(t4.w, w3.x, a0); a1 = fmaf(t4.w, w3.y, a1);
            }
            float v0 = fmaf(xxv.x, mf.x + a0, xv.x);
            float v1 = fmaf(xxv.y, mf.y + a1, xv.y);
            if (f == 0) {
                *(float2*)(xw + idx) = make_float2(v0, v1);
            } else {
                __nv_bfloat162 hp, lp;
                hp.x = __float2bfloat16(v0);
                hp.y = __float2bfloat16(v1);
                lp.x = __float2bfloat16(v0 - __bfloat162float(hp.x));
                lp.y = __float2bfloat16(v1 - __bfloat162float(hp.y));
                *(uint32_t*)(acthi + slotoff + idx) = *(uint32_t*)&hp;
                *(uint32_t*)(actlo + slotoff + idx) = *(uint32_t*)&lp;
            }
            idx += 4 * C_;
        }
        __syncthreads();
    }
}

// ==========================================================================
// WKV6 v2: 192 blocks (bh x i-half), 256 thr = 32 i x 8 j-groups.
// S[8]/thread, u-term fused inline, double-buffered smem, ONE sync per t.
// ==========================================================================
__global__ void __launch_bounds__(256)
k_wkv(const float* __restrict__ r, const float* __restrict__ k,
      const float* __restrict__ v, const float* __restrict__ wd,
      const float* __restrict__ u, float* __restrict__ y)
{
    const int bh2   = blockIdx.x;          // 0..191
    const int bh    = bh2 >> 1;
    const int ihalf = bh2 & 1;
    const int b = bh / H_, h = bh % H_;
    const int tid = threadIdx.x;
    const int il  = tid & 31;              // i within half
    const int jg  = tid >> 5;              // warp = j-group 0..7
    const int role = tid >> 6;             // 0..3 loader role
    const int rl   = tid & 63;

    __shared__ __align__(16) float sr[2][64];
    __shared__ __align__(16) float sk[2][64];
    __shared__ __align__(16) float sw[2][64];
    __shared__ __align__(16) float sv[2][32];
    __shared__ float part[2][8][32];

    float S[8];
#pragma unroll
    for (int jj = 0; jj < 8; jj++) S[jj] = 0.f;
    float uj[8];
#pragma unroll
    for (int jj = 0; jj < 8; jj++) uj[jj] = u[h * 64 + jg * 8 + jj];

    const size_t base = (size_t)b * T_ * C_ + h * 64;
    const float* srcp =
        (role == 0) ? (r  + base + rl) :
        (role == 1) ? (k  + base + rl) :
        (role == 2) ? (wd + base + rl) :
                      (v  + base + ihalf * 32 + (rl & 31));
    const bool doload = (role < 3) || (rl < 32);

    float cur = doload ? srcp[0]  : 0.f;
    float nxt = doload ? srcp[C_] : 0.f;   // t=1 (T_ >= 2)

    // write t=0 into buf 0
    if (role == 0)      sr[0][rl] = cur;
    else if (role == 1) sk[0][rl] = cur;
    else if (role == 2) sw[0][rl] = cur;
    else if (rl < 32)   sv[0][rl] = cur;
    __syncthreads();

    float* yout = y + base + ihalf * 32 + il;

    for (int t = 0; t < T_; t++) {
        const int buf = t & 1;
        const float vi = sv[buf][il];

        float rr[8], kk2[8], ww[8];
        *(float4*)(rr)      = *(const float4*)(&sr[buf][jg * 8]);
        *(float4*)(rr + 4)  = *(const float4*)(&sr[buf][jg * 8 + 4]);
        *(float4*)(kk2)     = *(const float4*)(&sk[buf][jg * 8]);
        *(float4*)(kk2 + 4) = *(const float4*)(&sk[buf][jg * 8 + 4]);
        *(float4*)(ww)      = *(const float4*)(&sw[buf][jg * 8]);
        *(float4*)(ww + 4)  = *(const float4*)(&sw[buf][jg * 8 + 4]);

        float yp = 0.f;
#pragma unroll
        for (int jj = 0; jj < 8; jj++) {
            float kv  = kk2[jj] * vi;
            float tmp = fmaf(uj[jj] * kk2[jj], vi, S[jj]);   // S + u*k*v
            yp = fmaf(rr[jj], tmp, yp);
            S[jj] = fmaf(ww[jj], S[jj], kv);
        }
        if (jg) part[buf][jg][il] = yp;

        if (t + 1 < T_) {
            // stage inputs for t+1 into the other buffer
            if (role == 0)      sr[buf ^ 1][rl] = nxt;
            else if (role == 1) sk[buf ^ 1][rl] = nxt;
            else if (role == 2) sw[buf ^ 1][rl] = nxt;
            else if (rl < 32)   sv[buf ^ 1][rl] = nxt;
            if (t + 2 < T_ && doload) nxt = srcp[(size_t)(t + 2) * C_];
        }
        __syncthreads();

        if (jg == 0) {
            float yv = yp;
#pragma unroll
            for (int p = 1; p < 8; p++) yv += part[buf][p][il];
            yout[(size_t)t * C_] = yv;
        }
    }
}

// ==========================================================================
// GroupNorm * g -> bf16 hi/lo split directly (for the W_o GEMM)
// ==========================================================================
__global__ void k_gnorm(const float* __restrict__ y, const float* __restrict__ gbuf,
                        const float* __restrict__ lnw, const float* __restrict__ lnb,
                        __nv_bfloat16* __restrict__ hi, __nv_bfloat16* __restrict__ lo)
{
    const int row = blockIdx.x;
    const int c   = threadIdx.x;
    size_t idx = (size_t)row * C_ + c;
    float v = y[idx];
    float s = v, s2 = v * v;
#pragma unroll
    for (int off = 16; off; off >>= 1) {
        s  += __shfl_xor_sync(0xffffffffu, s,  off);
        s2 += __shfl_xor_sync(0xffffffffu, s2, off);
    }
    __shared__ float as[24], as2[24];
    if ((c & 31) == 0) { as[c >> 5] = s; as2[c >> 5] = s2; }
    __syncthreads();
    const int g = c >> 6;
    float sum  = as[2 * g]  + as[2 * g + 1];
    float sum2 = as2[2 * g] + as2[2 * g + 1];
    float mu   = sum * (1.f / 64.f);
    float var  = sum2 * (1.f / 64.f) - mu * mu;
    float nv   = (v - mu) * rsqrtf(var + 1e-5f);
    float val  = fmaf(nv, lnw[c], lnb[c]) * gbuf[idx];
    __nv_bfloat16 h = __float2bfloat16(val);
    hi[idx] = h;
    lo[idx] = __float2bfloat16(val - __bfloat162float(h));
}

// ==========================================================================
// Host launcher
// ==========================================================================
extern "C" void kernel_launch(void* const* d_in, const int* in_sizes, int n_in,
                              void* d_out, int out_size)
{
    const float* x     = (const float*)d_in[0];
    const float* W_r   = (const float*)d_in[1];
    const float* W_k   = (const float*)d_in[2];
    const float* W_v   = (const float*)d_in[3];
    const float* W_g   = (const float*)d_in[4];
    const float* W_o   = (const float*)d_in[5];
    const float* maa_x = (const float*)d_in[6];
    const float* maa_w = (const float*)d_in[7];
    const float* maa_k = (const float*)d_in[8];
    const float* maa_v = (const float*)d_in[9];
    const float* maa_r = (const float*)d_in[10];
    const float* maa_g = (const float*)d_in[11];
    const float* maa_w1= (const float*)d_in[12];
    const float* maa_w2= (const float*)d_in[13];
    const float* tdec  = (const float*)d_in[14];
    const float* dec_w1= (const float*)d_in[15];
    const float* dec_w2= (const float*)d_in[16];
    const float* faaaa = (const float*)d_in[17];
    const float* ln_w  = (const float*)d_in[18];
    const float* ln_b  = (const float*)d_in[19];
    (void)in_sizes; (void)n_in; (void)out_size;

    float* S = nullptr;
    cudaGetSymbolAddress((void**)&S, g_scratch);
    __nv_bfloat16 *acthi = nullptr, *actlo = nullptr, *w5hi = nullptr, *w5lo = nullptr;
    cudaGetSymbolAddress((void**)&acthi, g_acthi);
    cudaGetSymbolAddress((void**)&actlo, g_actlo);
    cudaGetSymbolAddress((void**)&w5hi, g_w5hi);
    cudaGetSymbolAddress((void**)&w5lo, g_w5lo);

    float* xx   = S + OFF_XX;
    float* xxx  = S + OFF_XXX;
    float* t5   = S + OFF_T5;
    float* xw   = S + OFF_XW;
    float* rb   = S + OFF_R;
    float* kb   = S + OFF_K;
    float* vb   = S + OFF_V;
    float* h1   = S + OFF_H1;
    float* wdec = S + OFF_WDEC;
    float* yb   = S + OFF_Y;
    float* outp = (float*)d_out;

    // 0. split all 5 weights
    k_split5<<<(unsigned)(5 * WSZ_ / 4 / 256), 256>>>(W_r, W_k, W_v, W_g, W_o, w5hi, w5lo);

    // 1. shift + xxx (float4)
    k_shift<<<(unsigned)(NC_ / 4 / 256), 256>>>(x, maa_x, xx, xxx);

    // 2. t5 = tanh(xxx @ maa_w1)
    k_gemm<1, false><<<dim3(2, NR_ / 128), 256>>>(xxx, maa_w1, t5, NR_, 160, C_, nullptr);

    // 3. fused token mix -> xw fp32 + bf16 hi/lo for k,v,r,g
    k_mix<<<dim3(NR_ / 64, C_ / 128), 256>>>(x, xx, t5, maa_w2,
                                             maa_w, maa_k, maa_v, maa_r, maa_g,
                                             xw, acthi, actlo);

    // 4. batched r/k/v/g GEMMs in ONE launch (z = 0..3) -> rb,kb,vb,gb
    k_gemm_mma4<<<dim3(C_ / 128, NR_ / 128, 4), 256>>>(acthi, actlo, w5hi, w5lo, rb);

    // 5. decay path (small fp32 GEMMs)
    k_gemm<1, false><<<dim3(1, NR_ / 128), 256>>>(xw, dec_w1, h1, NR_, 64, C_, nullptr);
    k_gemm<3, false><<<dim3(C_ / 128, NR_ / 128), 256>>>(h1, dec_w2, wdec, NR_, C_, 64, tdec);

    // 6. wkv recurrence (u-term fused; 192 blocks)
    k_wkv<<<B_ * H_ * 2, 256>>>(rb, kb, vb, wdec, faaaa, yb);

    // 7. groupnorm * g -> bf16 pair (reuse act slot 0; gb = rb + 3*NC_)
    k_gnorm<<<NR_, C_>>>(yb, rb + 3 * NC_, ln_w, ln_b, acthi, actlo);

    // 8. out = yn @ W_o^T
    k_gemm_mma<<<dim3(C_ / 128, NR_ / 128), 256>>>(acthi, actlo,
                                                   w5hi + 4 * WSZ_, w5lo + 4 * WSZ_, outp, 0);
}

// round 14
// speedup vs baseline: 1.0561x; 1.0561x over previous
#include <cuda_runtime.h>
#include <cuda_bf16.h>
#include <math.h>
#include <stdint.h>

// ---------------- problem constants (fixed shapes) ----------------
#define B_   8
#define T_   1024
#define C_   768
#define H_   12
#define HS_  64
#define PH_  32
#define PW_  32
#define NR_  (B_ * T_)          // 8192 rows
#define NC_  ((size_t)NR_ * C_) // 6291456 elems
#define WSZ_ ((size_t)C_ * C_)  // 589824

// ---------------- scratch ----------------
__device__ __align__(16) float g_scratch[10 * NC_ + (size_t)NR_ * 160 + (size_t)NR_ * 64 + (size_t)NR_ * H_];
__device__ __align__(16) __nv_bfloat16 g_acthi[4 * NC_];   // slots: 0=k,1=v,2=r,3=g (slot0 also = xxx hi pre-mix)
__device__ __align__(16) __nv_bfloat16 g_actlo[4 * NC_];
__device__ __align__(16) __nv_bfloat16 g_w5hi[5 * WSZ_];   // W_r,W_k,W_v,W_g,W_o
__device__ __align__(16) __nv_bfloat16 g_w5lo[5 * WSZ_];
__device__ __align__(16) __nv_bfloat16 g_w1thi[160 * C_];  // maa_w1^T [160,768]
__device__ __align__(16) __nv_bfloat16 g_w1tlo[160 * C_];

#define OFF_XX   ((size_t)0)
#define OFF_XXX  (OFF_XX  + NC_)          // (unused as fp32 now; kept for layout)
#define OFF_T5   (OFF_XXX + NC_)
#define OFF_XW   (OFF_T5  + (size_t)NR_ * 160)
#define OFF_R    (OFF_XW  + NC_)          // R,K,V,G contiguous
#define OFF_K    (OFF_R   + NC_)
#define OFF_V    (OFF_K   + NC_)
#define OFF_G    (OFF_V   + NC_)
#define OFF_H1   (OFF_G   + NC_)
#define OFF_WDEC (OFF_H1  + (size_t)NR_ * 64)
#define OFF_Y    (OFF_WDEC+ NC_)
#define OFF_RUK  (OFF_Y   + NC_)

// ========================= helpers ==========================
__device__ __forceinline__ uint32_t smem_u32(const void* p) {
    uint32_t a;
    asm("{ .reg .u64 t; cvta.to.shared.u64 t, %1; cvt.u32.u64 %0, t; }" : "=r"(a) : "l"(p));
    return a;
}
__device__ __forceinline__ void ldsm_x4(uint32_t* r, uint32_t addr) {
    asm volatile("ldmatrix.sync.aligned.m8n8.x4.shared.b16 {%0,%1,%2,%3}, [%4];"
                 : "=r"(r[0]), "=r"(r[1]), "=r"(r[2]), "=r"(r[3]) : "r"(addr));
}
__device__ __forceinline__ void mma_bf16(float* c, const uint32_t* a, uint32_t b0, uint32_t b1) {
    asm volatile("mma.sync.aligned.m16n8k16.row.col.f32.bf16.bf16.f32 "
                 "{%0,%1,%2,%3}, {%4,%5,%6,%7}, {%8,%9}, {%0,%1,%2,%3};"
                 : "+f"(c[0]), "+f"(c[1]), "+f"(c[2]), "+f"(c[3])
                 : "r"(a[0]), "r"(a[1]), "r"(a[2]), "r"(a[3]), "r"(b0), "r"(b1));
}

// ==========================================================================
// bf16-split tensor-core GEMM body (N=768 full-tile version)
// ==========================================================================
#define PLANE_   2080
#define ATILE_   (4 * PLANE_)
#define BUFSZ_   (2 * ATILE_)

__device__ __forceinline__ void gemm_mma_body(
    const __nv_bfloat16* __restrict__ Ahi, const __nv_bfloat16* __restrict__ Alo,
    const __nv_bfloat16* __restrict__ Whi, const __nv_bfloat16* __restrict__ Wlo,
    float* __restrict__ Cmat, int doRelu, char* sm)
{
    const int tid  = threadIdx.x;
    const int warp = tid >> 5;
    const int lane = tid & 31;
    const int m0 = blockIdx.y * 128;
    const int n0 = blockIdx.x * 128;
    const int wm = warp >> 2;
    const int wn = warp & 3;

    float acc[4][4][4];
#pragma unroll
    for (int i = 0; i < 4; i++)
#pragma unroll
        for (int j = 0; j < 4; j++)
#pragma unroll
            for (int q = 0; q < 4; q++) acc[i][j][q] = 0.f;

    const int ldrow = tid >> 1;
    const int ldcb  = (tid & 1) * 2;

    uint4 ra[2], rb[2];

    const uint32_t sb = smem_u32(sm);
    const int lgrp = lane >> 3;
    const int lrl  = lane & 7;

#define LDG_T(c_)                                                               \
    {                                                                           \
        const int seg_ = (c_) / 24;                                             \
        const int kc_  = ((c_) % 24) * 32;                                      \
        const __nv_bfloat16* Ag = (seg_ == 1) ? Alo : Ahi;                      \
        const __nv_bfloat16* Bg = (seg_ == 2) ? Wlo : Whi;                      \
        const __nv_bfloat16* ap = Ag + (size_t)(m0 + ldrow) * C_ + kc_ + ldcb * 8; \
        const __nv_bfloat16* bp = Bg + (size_t)(n0 + ldrow) * C_ + kc_ + ldcb * 8; \
        ra[0] = *(const uint4*)ap; ra[1] = *(const uint4*)(ap + 8);             \
        rb[0] = *(const uint4*)bp; rb[1] = *(const uint4*)(bp + 8);             \
    }

#define STS_T(buf_)                                                             \
    {                                                                           \
        char* b_ = sm + (buf_) * BUFSZ_;                                        \
        *(uint4*)(b_ + (ldcb + 0) * PLANE_ + ldrow * 16) = ra[0];               \
        *(uint4*)(b_ + (ldcb + 1) * PLANE_ + ldrow * 16) = ra[1];               \
        *(uint4*)(b_ + ATILE_ + (ldcb + 0) * PLANE_ + ldrow * 16) = rb[0];      \
        *(uint4*)(b_ + ATILE_ + (ldcb + 1) * PLANE_ + ldrow * 16) = rb[1];      \
    }

    LDG_T(0);
    STS_T(0);
    __syncthreads();

    for (int c = 0; c < 72; c++) {
        const int buf = c & 1;
        const bool hasNext = (c + 1 < 72);
        if (hasNext) LDG_T(c + 1);

        const uint32_t abase = sb + buf * BUFSZ_;
        const uint32_t bbase = abase + ATILE_;

#pragma unroll
        for (int kk = 0; kk < 2; kk++) {
            uint32_t afr[4][4], bfr[2][4];
#pragma unroll
            for (int mt = 0; mt < 4; mt++) {
                int row   = wm * 64 + mt * 16 + (lgrp & 1) * 8 + lrl;
                int chunk = kk * 2 + (lgrp >> 1);
                ldsm_x4(afr[mt], abase + chunk * PLANE_ + row * 16);
            }
#pragma unroll
            for (int nt = 0; nt < 2; nt++) {
                int nr    = wn * 32 + nt * 16 + (lgrp >> 1) * 8 + lrl;
                int chunk = kk * 2 + (lgrp & 1);
                ldsm_x4(bfr[nt], bbase + chunk * PLANE_ + nr * 16);
            }
#pragma unroll
            for (int mt = 0; mt < 4; mt++)
#pragma unroll
                for (int ng = 0; ng < 4; ng++)
                    mma_bf16(acc[mt][ng], afr[mt], bfr[ng >> 1][(ng & 1) * 2 + 0],
                             bfr[ng >> 1][(ng & 1) * 2 + 1]);
        }

        if (hasNext) {
            STS_T(buf ^ 1);
            __syncthreads();
        }
    }
#undef LDG_T
#undef STS_T

#pragma unroll
    for (int mt = 0; mt < 4; mt++) {
        const int r0 = m0 + wm * 64 + mt * 16 + (lane >> 2);
#pragma unroll
        for (int ng = 0; ng < 4; ng++) {
            const int col = n0 + wn * 32 + ng * 8 + (lane & 3) * 2;
            float c0 = acc[mt][ng][0], c1 = acc[mt][ng][1];
            float c2 = acc[mt][ng][2], c3 = acc[mt][ng][3];
            if (doRelu) {
                c0 = fmaxf(c0, 0.f); c1 = fmaxf(c1, 0.f);
                c2 = fmaxf(c2, 0.f); c3 = fmaxf(c3, 0.f);
            }
            *(float2*)(Cmat + (size_t)r0 * C_ + col)       = make_float2(c0, c1);
            *(float2*)(Cmat + (size_t)(r0 + 8) * C_ + col) = make_float2(c2, c3);
        }
    }
}

// Batched r/k/v/g GEMMs: gridDim.z = 4 selects act slot / weight / output.
__global__ void __launch_bounds__(256, 2)
k_gemm_mma4(const __nv_bfloat16* __restrict__ acthi, const __nv_bfloat16* __restrict__ actlo,
            const __nv_bfloat16* __restrict__ w5hi, const __nv_bfloat16* __restrict__ w5lo,
            float* __restrict__ outbase)
{
    __shared__ __align__(16) char sm[2 * BUFSZ_];
    const int z = blockIdx.z;
    const int aslot = (z == 0) ? 2 : (z == 1) ? 0 : (z == 2) ? 1 : 3;
    gemm_mma_body(acthi + (size_t)aslot * NC_, actlo + (size_t)aslot * NC_,
                  w5hi + (size_t)z * WSZ_, w5lo + (size_t)z * WSZ_,
                  outbase + (size_t)z * NC_, z == 3, sm);
}

// Single GEMM (W_o path)
__global__ void __launch_bounds__(256, 2)
k_gemm_mma(const __nv_bfloat16* __restrict__ Ahi, const __nv_bfloat16* __restrict__ Alo,
           const __nv_bfloat16* __restrict__ Whi, const __nv_bfloat16* __restrict__ Wlo,
           float* __restrict__ Cmat, int doRelu)
{
    __shared__ __align__(16) char sm[2 * BUFSZ_];
    gemm_mma_body(Ahi, Alo, Whi, Wlo, Cmat, doRelu, sm);
}

// ==========================================================================
// t5 GEMM via mma: t5[8192,160] = tanh( xxx @ maa_w1 ), N=160 guarded.
// A = xxx hi/lo [NR_,768]; W = w1t hi/lo [160,768]. grid (2, 64).
// ==========================================================================
__global__ void __launch_bounds__(256, 2)
k_gemm_mma_t5(const __nv_bfloat16* __restrict__ Ahi, const __nv_bfloat16* __restrict__ Alo,
              const __nv_bfloat16* __restrict__ Whi, const __nv_bfloat16* __restrict__ Wlo,
              float* __restrict__ out)
{
    __shared__ __align__(16) char sm[2 * BUFSZ_];
    const int tid  = threadIdx.x;
    const int warp = tid >> 5;
    const int lane = tid & 31;
    const int m0 = blockIdx.y * 128;
    const int n0 = blockIdx.x * 128;
    const int wm = warp >> 2;
    const int wn = warp & 3;

    float acc[4][4][4];
#pragma unroll
    for (int i = 0; i < 4; i++)
#pragma unroll
        for (int j = 0; j < 4; j++)
#pragma unroll
            for (int q = 0; q < 4; q++) acc[i][j][q] = 0.f;

    const int ldrow = tid >> 1;
    const int ldcb  = (tid & 1) * 2;
    const bool bok  = (n0 + ldrow) < 160;
    const uint4 z4  = make_uint4(0u, 0u, 0u, 0u);

    uint4 ra[2], rb[2];
    const uint32_t sb = smem_u32(sm);
    const int lgrp = lane >> 3;
    const int lrl  = lane & 7;

#define LDG_T5(c_)                                                              \
    {                                                                           \
        const int seg_ = (c_) / 24;                                             \
        const int kc_  = ((c_) % 24) * 32;                                      \
        const __nv_bfloat16* Ag = (seg_ == 1) ? Alo : Ahi;                      \
        const __nv_bfloat16* Bg = (seg_ == 2) ? Wlo : Whi;                      \
        const __nv_bfloat16* ap = Ag + (size_t)(m0 + ldrow) * C_ + kc_ + ldcb * 8; \
        ra[0] = *(const uint4*)ap; ra[1] = *(const uint4*)(ap + 8);             \
        if (bok) {                                                              \
            const __nv_bfloat16* bp = Bg + (size_t)(n0 + ldrow) * C_ + kc_ + ldcb * 8; \
            rb[0] = *(const uint4*)bp; rb[1] = *(const uint4*)(bp + 8);         \
        } else { rb[0] = z4; rb[1] = z4; }                                      \
    }

#define STS_T5(buf_)                                                            \
    {                                                                           \
        char* b_ = sm + (buf_) * BUFSZ_;                                        \
        *(uint4*)(b_ + (ldcb + 0) * PLANE_ + ldrow * 16) = ra[0];               \
        *(uint4*)(b_ + (ldcb + 1) * PLANE_ + ldrow * 16) = ra[1];               \
        *(uint4*)(b_ + ATILE_ + (ldcb + 0) * PLANE_ + ldrow * 16) = rb[0];      \
        *(uint4*)(b_ + ATILE_ + (ldcb + 1) * PLANE_ + ldrow * 16) = rb[1];      \
    }

    LDG_T5(0);
    STS_T5(0);
    __syncthreads();

    for (int c = 0; c < 72; c++) {
        const int buf = c & 1;
        const bool hasNext = (c + 1 < 72);
        if (hasNext) LDG_T5(c + 1);

        const uint32_t abase = sb + buf * BUFSZ_;
        const uint32_t bbase = abase + ATILE_;

#pragma unroll
        for (int kk = 0; kk < 2; kk++) {
            uint32_t afr[4][4], bfr[2][4];
#pragma unroll
            for (int mt = 0; mt < 4; mt++) {
                int row   = wm * 64 + mt * 16 + (lgrp & 1) * 8 + lrl;
                int chunk = kk * 2 + (lgrp >> 1);
                ldsm_x4(afr[mt], abase + chunk * PLANE_ + row * 16);
            }
#pragma unroll
            for (int nt = 0; nt < 2; nt++) {
                int nr    = wn * 32 + nt * 16 + (lgrp >> 1) * 8 + lrl;
                int chunk = kk * 2 + (lgrp & 1);
                ldsm_x4(bfr[nt], bbase + chunk * PLANE_ + nr * 16);
            }
#pragma unroll
            for (int mt = 0; mt < 4; mt++)
#pragma unroll
                for (int ng = 0; ng < 4; ng++)
                    mma_bf16(acc[mt][ng], afr[mt], bfr[ng >> 1][(ng & 1) * 2 + 0],
                             bfr[ng >> 1][(ng & 1) * 2 + 1]);
        }

        if (hasNext) {
            STS_T5(buf ^ 1);
            __syncthreads();
        }
    }
#undef LDG_T5
#undef STS_T5

#pragma unroll
    for (int mt = 0; mt < 4; mt++) {
        const int r0 = m0 + wm * 64 + mt * 16 + (lane >> 2);
#pragma unroll
        for (int ng = 0; ng < 4; ng++) {
            const int col = n0 + wn * 32 + ng * 8 + (lane & 3) * 2;
            if (col < 160) {
                float c0 = tanhf(acc[mt][ng][0]), c1 = tanhf(acc[mt][ng][1]);
                float c2 = tanhf(acc[mt][ng][2]), c3 = tanhf(acc[mt][ng][3]);
                *(float2*)(out + (size_t)r0 * 160 + col)       = make_float2(c0, c1);
                *(float2*)(out + (size_t)(r0 + 8) * 160 + col) = make_float2(c2, c3);
            }
        }
    }
}

// ==========================================================================
// Split all five weight matrices into bf16 hi/lo once (float4 vectorized).
// ==========================================================================
__global__ void __launch_bounds__(256)
k_split5(const float* __restrict__ w0, const float* __restrict__ w1,
         const float* __restrict__ w2, const float* __restrict__ w3,
         const float* __restrict__ w4,
         __nv_bfloat16* __restrict__ hi, __nv_bfloat16* __restrict__ lo)
{
    size_t i4 = (size_t)blockIdx.x * blockDim.x + threadIdx.x;
    size_t idx = i4 * 4;
    int sel = (int)(idx / WSZ_);
    size_t off = idx % WSZ_;
    const float* src = (sel == 0) ? w0 : (sel == 1) ? w1 : (sel == 2) ? w2 : (sel == 3) ? w3 : w4;
    float4 a = *(const float4*)(src + off);
    __nv_bfloat16 h0 = __float2bfloat16(a.x);
    __nv_bfloat16 h1 = __float2bfloat16(a.y);
    __nv_bfloat16 h2 = __float2bfloat16(a.z);
    __nv_bfloat16 h3 = __float2bfloat16(a.w);
    __nv_bfloat162 hp0, hp1, lp0, lp1;
    hp0.x = h0; hp0.y = h1; hp1.x = h2; hp1.y = h3;
    lp0.x = __float2bfloat16(a.x - __bfloat162float(h0));
    lp0.y = __float2bfloat16(a.y - __bfloat162float(h1));
    lp1.x = __float2bfloat16(a.z - __bfloat162float(h2));
    lp1.y = __float2bfloat16(a.w - __bfloat162float(h3));
    *(uint2*)(hi + idx) = make_uint2(*(uint32_t*)&hp0, *(uint32_t*)&hp1);
    *(uint2*)(lo + idx) = make_uint2(*(uint32_t*)&lp0, *(uint32_t*)&lp1);
}

// ==========================================================================
// Transpose + split maa_w1 [768,160] -> w1t hi/lo [160,768]
// ==========================================================================
__global__ void __launch_bounds__(256)
k_splitw1t(const float* __restrict__ w1,
           __nv_bfloat16* __restrict__ hi, __nv_bfloat16* __restrict__ lo)
{
    int idx = blockIdx.x * 256 + threadIdx.x;   // < 160*768
    int n  = idx / C_;
    int kk = idx % C_;
    float a = w1[(size_t)kk * 160 + n];
    __nv_bfloat16 h = __float2bfloat16(a);
    hi[idx] = h;
    lo[idx] = __float2bfloat16(a - __bfloat162float(h));
}

// ==========================================================================
// Kernel 1: q-shift (float4) -> xx fp32 ; xxx emitted as bf16 hi/lo
// ==========================================================================
__global__ void __launch_bounds__(256)
k_shift(const float* __restrict__ x, const float* __restrict__ maa_x,
        float* __restrict__ xx,
        __nv_bfloat16* __restrict__ xhi, __nv_bfloat16* __restrict__ xlo)
{
    size_t i4 = (size_t)blockIdx.x * blockDim.x + threadIdx.x;
    size_t idx = i4 * 4;
    int c  = (int)(idx % C_);
    int bt = (int)(idx / C_);
    int t  = bt % T_;
    int w  = t % PW_;
    int h  = t / PW_;
    int quarter = (c & (HS_ - 1)) >> 4;

    float4 src = make_float4(0.f, 0.f, 0.f, 0.f);
    if (quarter == 0)      { if (w > 0)       src = *(const float4*)(x + idx - C_); }
    else if (quarter == 1) { if (w < PW_ - 1) src = *(const float4*)(x + idx + C_); }
    else if (quarter == 2) { if (h > 0)       src = *(const float4*)(x + idx - PW_ * C_); }
    else                   { if (h < PH_ - 1) src = *(const float4*)(x + idx + PW_ * C_); }

    float4 xv = *(const float4*)(x + idx);
    float4 mv = *(const float4*)(maa_x + c);
    float4 d, o;
    d.x = src.x - xv.x; d.y = src.y - xv.y; d.z = src.z - xv.z; d.w = src.w - xv.w;
    o.x = fmaf(d.x, mv.x, xv.x); o.y = fmaf(d.y, mv.y, xv.y);
    o.z = fmaf(d.z, mv.z, xv.z); o.w = fmaf(d.w, mv.w, xv.w);
    *(float4*)(xx + idx) = d;

    __nv_bfloat162 hp0, hp1, lp0, lp1;
    hp0.x = __float2bfloat16(o.x); hp0.y = __float2bfloat16(o.y);
    hp1.x = __float2bfloat16(o.z); hp1.y = __float2bfloat16(o.w);
    lp0.x = __float2bfloat16(o.x - __bfloat162float(hp0.x));
    lp0.y = __float2bfloat16(o.y - __bfloat162float(hp0.y));
    lp1.x = __float2bfloat16(o.z - __bfloat162float(hp1.x));
    lp1.y = __float2bfloat16(o.w - __bfloat162float(hp1.y));
    *(uint2*)(xhi + idx) = make_uint2(*(uint32_t*)&hp0, *(uint32_t*)&hp1);
    *(uint2*)(xlo + idx) = make_uint2(*(uint32_t*)&lp0, *(uint32_t*)&lp1);
}

// ==========================================================================
// Pipelined tiled fp32 GEMM (decay path only now)
// ==========================================================================
template<int EPI, bool BNT>
__global__ void __launch_bounds__(256, 2)
k_gemm(const float* __restrict__ A, const float* __restrict__ B,
       float* __restrict__ Cmat, int M, int N, int K, const float* __restrict__ bias)
{
    __shared__ float As[2][16][132];
    __shared__ float Bs[2][16][132];

    const int m0   = blockIdx.y * 128;
    const int n0   = blockIdx.x * 128;
    const int tid  = threadIdx.x;
    const int warp = tid >> 5;
    const int lane = tid & 31;
    const int tm   = (warp >> 2) * 64 + (lane >> 2) * 8;
    const int tn   = (warp & 3) * 32 + (lane & 3) * 8;

    float acc[8][8];
#pragma unroll
    for (int i = 0; i < 8; i++)
#pragma unroll
        for (int j = 0; j < 8; j++) acc[i][j] = 0.f;

    float4 aR[2], bR[2];

#define LDG_TILE(k0_)                                                          \
    {                                                                          \
        _Pragma("unroll")                                                      \
        for (int l = 0; l < 2; l++) {                                          \
            int e  = tid + l * 256;                                            \
            int am = e >> 2;                                                   \
            int ak = (e & 3) * 4;                                              \
            aR[l] = *(const float4*)(A + (size_t)(m0 + am) * K + (k0_) + ak);  \
            if (BNT) {                                                         \
                int bn = e >> 2;                                               \
                int bk = (e & 3) * 4;                                          \
                bR[l] = make_float4(0.f, 0.f, 0.f, 0.f);                       \
                if (n0 + bn < N)                                               \
                    bR[l] = *(const float4*)(B + (size_t)(n0 + bn) * K + (k0_) + bk); \
            } else {                                                           \
                int bk = e >> 5;                                               \
                int bn = (e & 31) * 4;                                         \
                bR[l] = make_float4(0.f, 0.f, 0.f, 0.f);                       \
                if (n0 + bn < N)                                               \
                    bR[l] = *(const float4*)(B + (size_t)((k0_) + bk) * N + n0 + bn); \
            }                                                                  \
        }                                                                      \
    }

#define STS_TILE(buf_)                                                         \
    {                                                                          \
        _Pragma("unroll")                                                      \
        for (int l = 0; l < 2; l++) {                                          \
            int e  = tid + l * 256;                                            \
            int am = e >> 2;                                                   \
            int ak = (e & 3) * 4;                                              \
            As[buf_][ak + 0][am] = aR[l].x; As[buf_][ak + 1][am] = aR[l].y;    \
            As[buf_][ak + 2][am] = aR[l].z; As[buf_][ak + 3][am] = aR[l].w;    \
            if (BNT) {                                                         \
                int bn = e >> 2;                                               \
                int bk = (e & 3) * 4;                                          \
                Bs[buf_][bk + 0][bn] = bR[l].x; Bs[buf_][bk + 1][bn] = bR[l].y;\
                Bs[buf_][bk + 2][bn] = bR[l].z; Bs[buf_][bk + 3][bn] = bR[l].w;\
            } else {                                                           \
                int bk = e >> 5;                                               \
                int bn = (e & 31) * 4;                                         \
                *(float4*)(&Bs[buf_][bk][bn]) = bR[l];                         \
            }                                                                  \
        }                                                                      \
    }

    LDG_TILE(0);
    STS_TILE(0);
    __syncthreads();

    int buf = 0;
    for (int k0 = 0; k0 < K; k0 += 16) {
        const bool hasNext = (k0 + 16 < K);
        if (hasNext) LDG_TILE(k0 + 16);

#pragma unroll
        for (int kk = 0; kk < 16; kk++) {
            float a[8], b[8];
            *(float4*)(a)     = *(const float4*)(&As[buf][kk][tm]);
            *(float4*)(a + 4) = *(const float4*)(&As[buf][kk][tm + 4]);
            *(float4*)(b)     = *(const float4*)(&Bs[buf][kk][tn]);
            *(float4*)(b + 4) = *(const float4*)(&Bs[buf][kk][tn + 4]);
#pragma unroll
            for (int i = 0; i < 8; i++)
#pragma unroll
                for (int j = 0; j < 8; j++)
                    acc[i][j] = fmaf(a[i], b[j], acc[i][j]);
        }

        if (hasNext) {
            STS_TILE(buf ^ 1);
            __syncthreads();
            buf ^= 1;
        }
    }
#undef LDG_TILE
#undef STS_TILE

#pragma unroll
    for (int i = 0; i < 8; i++) {
        int m = m0 + tm + i;
#pragma unroll
        for (int j = 0; j < 8; j++) {
            int n = n0 + tn + j;
            if (n < N) {
                float v = acc[i][j];
                if (EPI == 1) v = tanhf(v);
                else if (EPI == 2) v = fmaxf(v, 0.f);
                else if (EPI == 3) v = expf(-expf(bias[n] + v));
                Cmat[(size_t)m * N + n] = v;
            }
        }
    }
}

// ==========================================================================
// Fused token-mix v4 (R10/R11 winner, unchanged)
// ==========================================================================
__global__ void __launch_bounds__(256, 2)
k_mix(const float* __restrict__ x, const float* __restrict__ xx,
      const float* __restrict__ t5, const float* __restrict__ w2,
      const float* __restrict__ ma0, const float* __restrict__ ma1,
      const float* __restrict__ ma2, const float* __restrict__ ma3,
      const float* __restrict__ ma4,
      float* __restrict__ xw,
      __nv_bfloat16* __restrict__ acthi, __nv_bfloat16* __restrict__ actlo)
{
    const int r0  = blockIdx.x * 64;
    const int c0  = blockIdx.y * 128;
    const int tid = threadIdx.x;
    const int cp  = (tid & 63) * 2;
    const int rh  = tid >> 6;

    __shared__ __align__(16) float tsh[64][36];

    float2 mfv[5];
    mfv[0] = *(const float2*)(ma0 + c0 + cp);
    mfv[1] = *(const float2*)(ma1 + c0 + cp);
    mfv[2] = *(const float2*)(ma2 + c0 + cp);
    mfv[3] = *(const float2*)(ma3 + c0 + cp);
    mfv[4] = *(const float2*)(ma4 + c0 + cp);

    for (int f = 0; f < 5; f++) {
#pragma unroll
        for (int l = 0; l < 8; l++) {
            int e = tid + l * 256;
            tsh[e >> 5][e & 31] = t5[(size_t)(r0 + (e >> 5)) * 160 + f * 32 + (e & 31)];
        }
        float2 wreg[32];
#pragma unroll
        for (int rr = 0; rr < 32; rr++)
            wreg[rr] = *(const float2*)(w2 + (size_t)(f * 32 + rr) * C_ + c0 + cp);
        __syncthreads();

        const float2 mf = mfv[f];
        const size_t slotoff = (size_t)(f - 1) * NC_;
        size_t idx = (size_t)(r0 + rh) * C_ + c0 + cp;

#pragma unroll 4
        for (int it = 0; it < 16; it++) {
            const int row = rh + it * 4;
            float2 xv  = *(const float2*)(x + idx);
            float2 xxv = *(const float2*)(xx + idx);
            const float4* trow = (const float4*)(&tsh[row][0]);
            float a0 = 0.f, a1 = 0.f;
#pragma unroll
            for (int q = 0; q < 8; q++) {
                float4 t4 = trow[q];
                float2 w0 = wreg[4 * q + 0], w1 = wreg[4 * q + 1];
                float2 w2r = wreg[4 * q + 2], w3 = wreg[4 * q + 3];
                a0 = fmaf(t4.x, w0.x, a0); a1 = fmaf(t4.x, w0.y, a1);
                a0 = fmaf(t4.y, w1.x, a0); a1 = fmaf(t4.y, w1.y, a1);
                a0 = fmaf(t4.z, w2r.x, a0); a1 = fmaf(t4.z, w2r.y, a1);
                a0 = fmaf(t4.w, w3.x, a0); a1 = fmaf(t4.w, w3.y, a1);
            }
            float v0 = fmaf(xxv.x, mf.x + a0, xv.x);
            float v1 = fmaf(xxv.y, mf.y + a1, xv.y);
            if (f == 0) {
                *(float2*)(xw + idx) = make_float2(v0, v1);
            } else {
                __nv_bfloat162 hp, lp;
                hp.x = __float2bfloat16(v0);
                hp.y = __float2bfloat16(v1);
                lp.x = __float2bfloat16(v0 - __bfloat162float(hp.x));
                lp.y = __float2bfloat16(v1 - __bfloat162float(hp.y));
                *(uint32_t*)(acthi + slotoff + idx) = *(uint32_t*)&hp;
                *(uint32_t*)(actlo + slotoff + idx) = *(uint32_t*)&lp;
            }
            idx += 4 * C_;
        }
        __syncthreads();
    }
}

// ==========================================================================
// ruk[row,h] = sum_j r*u*k   (R11 version)
// ==========================================================================
__global__ void k_ruk(const float* __restrict__ r, const float* __restrict__ k,
                      const float* __restrict__ u, float* __restrict__ ruk)
{
    const int row = blockIdx.x;
    const int c   = threadIdx.x;
    const int h   = c >> 6;
    const int j   = c & 63;
    size_t idx = (size_t)row * C_ + c;
    float p = r[idx] * u[c] * k[idx];
#pragma unroll
    for (int off = 16; off; off >>= 1) p += __shfl_xor_sync(0xffffffffu, p, off);
    __shared__ float ws[24];
    if ((c & 31) == 0) ws[c >> 5] = p;
    __syncthreads();
    if (j == 0) ruk[(size_t)row * H_ + h] = ws[2 * h] + ws[2 * h + 1];
}

// ==========================================================================
// WKV6 recurrence (R11 version: 96 blocks, 256 thr, j quarters, 2 syncs)
// ==========================================================================
__global__ void __launch_bounds__(256)
k_wkv(const float* __restrict__ r, const float* __restrict__ k,
      const float* __restrict__ v, const float* __restrict__ wd,
      const float* __restrict__ ruk, float* __restrict__ y)
{
    const int bh = blockIdx.x;
    const int b  = bh / H_;
    const int h  = bh % H_;
    const int tid = threadIdx.x;
    const int i  = tid & 63;
    const int q  = tid >> 6;

    __shared__ __align__(16) float sr[64];
    __shared__ __align__(16) float sk[64];
    __shared__ __align__(16) float sw[64];
    __shared__ __align__(16) float sv[64];
    __shared__ float part[3][64];

    float S[16];
#pragma unroll
    for (int jj = 0; jj < 16; jj++) S[jj] = 0.f;

    const size_t base  = (size_t)b * T_ * C_ + h * 64;
    const size_t rbase = (size_t)b * T_ * H_ + h;

    const float* mysrc = (q == 0) ? r : (q == 1) ? k : (q == 2) ? wd : v;
    float cur = mysrc[base + i];

    for (int t = 0; t < T_; t++) {
        if (q == 0)      sr[i] = cur;
        else if (q == 1) sk[i] = cur;
        else if (q == 2) sw[i] = cur;
        else             sv[i] = cur;
        __syncthreads();

        float nxt = cur;
        if (t + 1 < T_) nxt = mysrc[base + (size_t)(t + 1) * C_ + i];

        const float vi = sv[i];
        float yp = 0.f;
#pragma unroll
        for (int g4 = 0; g4 < 4; g4++) {
            float4 r4 = *(const float4*)(sr + q * 16 + g4 * 4);
            float4 k4 = *(const float4*)(sk + q * 16 + g4 * 4);
            float4 w4 = *(const float4*)(sw + q * 16 + g4 * 4);
            float kv;
            kv = k4.x * vi; yp = fmaf(r4.x, S[4*g4+0], yp); S[4*g4+0] = fmaf(w4.x, S[4*g4+0], kv);
            kv = k4.y * vi; yp = fmaf(r4.y, S[4*g4+1], yp); S[4*g4+1] = fmaf(w4.y, S[4*g4+1], kv);
            kv = k4.z * vi; yp = fmaf(r4.z, S[4*g4+2], yp); S[4*g4+2] = fmaf(w4.z, S[4*g4+2], kv);
            kv = k4.w * vi; yp = fmaf(r4.w, S[4*g4+3], yp); S[4*g4+3] = fmaf(w4.w, S[4*g4+3], kv);
        }
        if (q) part[q - 1][i] = yp;
        __syncthreads();

        if (q == 0) {
            float yv = yp + part[0][i] + part[1][i] + part[2][i];
            yv = fmaf(ruk[rbase + (size_t)t * H_], vi, yv);
            y[base + (size_t)t * C_ + i] = yv;
        }
        cur = nxt;
    }
}

// ==========================================================================
// GroupNorm * g -> bf16 hi/lo split directly (for the W_o GEMM)
// ==========================================================================
__global__ void k_gnorm(const float* __restrict__ y, const float* __restrict__ gbuf,
                        const float* __restrict__ lnw, const float* __restrict__ lnb,
                        __nv_bfloat16* __restrict__ hi, __nv_bfloat16* __restrict__ lo)
{
    const int row = blockIdx.x;
    const int c   = threadIdx.x;
    size_t idx = (size_t)row * C_ + c;
    float v = y[idx];
    float s = v, s2 = v * v;
#pragma unroll
    for (int off = 16; off; off >>= 1) {
        s  += __shfl_xor_sync(0xffffffffu, s,  off);
        s2 += __shfl_xor_sync(0xffffffffu, s2, off);
    }
    __shared__ float as[24], as2[24];
    if ((c & 31) == 0) { as[c >> 5] = s; as2[c >> 5] = s2; }
    __syncthreads();
    const int g = c >> 6;
    float sum  = as[2 * g]  + as[2 * g + 1];
    float sum2 = as2[2 * g] + as2[2 * g + 1];
    float mu   = sum * (1.f / 64.f);
    float var  = sum2 * (1.f / 64.f) - mu * mu;
    float nv   = (v - mu) * rsqrtf(var + 1e-5f);
    float val  = fmaf(nv, lnw[c], lnb[c]) * gbuf[idx];
    __nv_bfloat16 h = __float2bfloat16(val);
    hi[idx] = h;
    lo[idx] = __float2bfloat16(val - __bfloat162float(h));
}

// ==========================================================================
// Host launcher
// ==========================================================================
extern "C" void kernel_launch(void* const* d_in, const int* in_sizes, int n_in,
                              void* d_out, int out_size)
{
    const float* x     = (const float*)d_in[0];
    const float* W_r   = (const float*)d_in[1];
    const float* W_k   = (const float*)d_in[2];
    const float* W_v   = (const float*)d_in[3];
    const float* W_g   = (const float*)d_in[4];
    const float* W_o   = (const float*)d_in[5];
    const float* maa_x = (const float*)d_in[6];
    const float* maa_w = (const float*)d_in[7];
    const float* maa_k = (const float*)d_in[8];
    const float* maa_v = (const float*)d_in[9];
    const float* maa_r = (const float*)d_in[10];
    const float* maa_g = (const float*)d_in[11];
    const float* maa_w1= (const float*)d_in[12];
    const float* maa_w2= (const float*)d_in[13];
    const float* tdec  = (const float*)d_in[14];
    const float* dec_w1= (const float*)d_in[15];
    const float* dec_w2= (const float*)d_in[16];
    const float* faaaa = (const float*)d_in[17];
    const float* ln_w  = (const float*)d_in[18];
    const float* ln_b  = (const float*)d_in[19];
    (void)in_sizes; (void)n_in; (void)out_size;

    float* S = nullptr;
    cudaGetSymbolAddress((void**)&S, g_scratch);
    __nv_bfloat16 *acthi = nullptr, *actlo = nullptr, *w5hi = nullptr, *w5lo = nullptr;
    __nv_bfloat16 *w1thi = nullptr, *w1tlo = nullptr;
    cudaGetSymbolAddress((void**)&acthi, g_acthi);
    cudaGetSymbolAddress((void**)&actlo, g_actlo);
    cudaGetSymbolAddress((void**)&w5hi, g_w5hi);
    cudaGetSymbolAddress((void**)&w5lo, g_w5lo);
    cudaGetSymbolAddress((void**)&w1thi, g_w1thi);
    cudaGetSymbolAddress((void**)&w1tlo, g_w1tlo);

    float* xx   = S + OFF_XX;
    float* t5   = S + OFF_T5;
    float* xw   = S + OFF_XW;
    float* rb   = S + OFF_R;
    float* kb   = S + OFF_K;
    float* vb   = S + OFF_V;
    float* h1   = S + OFF_H1;
    float* wdec = S + OFF_WDEC;
    float* yb   = S + OFF_Y;
    float* ruk  = S + OFF_RUK;
    float* outp = (float*)d_out;

    // 0. split all 5 weights + transpose-split maa_w1
    k_split5<<<(unsigned)(5 * WSZ_ / 4 / 256), 256>>>(W_r, W_k, W_v, W_g, W_o, w5hi, w5lo);
    k_splitw1t<<<(160 * C_) / 256, 256>>>(maa_w1, w1thi, w1tlo);

    // 1. shift: xx fp32 + xxx bf16 hi/lo (into act slot 0; consumed before k_mix)
    k_shift<<<(unsigned)(NC_ / 4 / 256), 256>>>(x, maa_x, xx, acthi, actlo);

    // 2. t5 = tanh(xxx @ maa_w1)   (tensor path)
    k_gemm_mma_t5<<<dim3(2, NR_ / 128), 256>>>(acthi, actlo, w1thi, w1tlo, t5);

    // 3. fused token mix -> xw fp32 + bf16 hi/lo for k,v,r,g
    k_mix<<<dim3(NR_ / 64, C_ / 128), 256>>>(x, xx, t5, maa_w2,
                                             maa_w, maa_k, maa_v, maa_r, maa_g,
                                             xw, acthi, actlo);

    // 4. batched r/k/v/g GEMMs in ONE launch (z = 0..3) -> rb,kb,vb,gb
    k_gemm_mma4<<<dim3(C_ / 128, NR_ / 128, 4), 256>>>(acthi, actlo, w5hi, w5lo, rb);

    // 5. decay path (small fp32 GEMMs)
    k_gemm<1, false><<<dim3(1, NR_ / 128), 256>>>(xw, dec_w1, h1, NR_, 64, C_, nullptr);
    k_gemm<3, false><<<dim3(C_ / 128, NR_ / 128), 256>>>(h1, dec_w2, wdec, NR_, C_, 64, tdec);

    // 6. wkv recurrence (R11 config)
    k_ruk<<<NR_, C_>>>(rb, kb, faaaa, ruk);
    k_wkv<<<B_ * H_, 256>>>(rb, kb, vb, wdec, ruk, yb);

    // 7. groupnorm * g -> bf16 pair (reuse act slot 0; gb = rb + 3*NC_)
    k_gnorm<<<NR_, C_>>>(yb, rb + 3 * NC_, ln_w, ln_b, acthi, actlo);

    // 8. out = yn @ W_o^T
    k_gemm_mma<<<dim3(C_ / 128, NR_ / 128), 256>>>(acthi, actlo,
                                                   w5hi + 4 * WSZ_, w5lo + 4 * WSZ_, outp, 0);
}

// round 16
// speedup vs baseline: 1.1180x; 1.0586x over previous
#include <cuda_runtime.h>
#include <cuda_bf16.h>
#include <math.h>
#include <stdint.h>

// ---------------- problem constants (fixed shapes) ----------------
#define B_   8
#define T_   1024
#define C_   768
#define H_   12
#define HS_  64
#define PH_  32
#define PW_  32
#define NR_  (B_ * T_)          // 8192 rows
#define NC_  ((size_t)NR_ * C_) // 6291456 elems
#define WSZ_ ((size_t)C_ * C_)  // 589824

// ---------------- scratch ----------------
__device__ __align__(16) float g_scratch[10 * NC_ + (size_t)NR_ * 160 + (size_t)NR_ * 64 + (size_t)NR_ * H_];
__device__ __align__(16) __nv_bfloat16 g_acthi[4 * NC_];   // slots: 0=k,1=v,2=r,3=g (slot0 also = xxx hi pre-mix)
__device__ __align__(16) __nv_bfloat16 g_actlo[4 * NC_];
__device__ __align__(16) __nv_bfloat16 g_w5hi[5 * WSZ_];   // W_r,W_k,W_v,W_g,W_o
__device__ __align__(16) __nv_bfloat16 g_w5lo[5 * WSZ_];
__device__ __align__(16) __nv_bfloat16 g_w1thi[160 * C_];  // maa_w1^T [160,768]
__device__ __align__(16) __nv_bfloat16 g_w1tlo[160 * C_];

#define OFF_XX   ((size_t)0)
#define OFF_XXX  (OFF_XX  + NC_)
#define OFF_T5   (OFF_XXX + NC_)
#define OFF_XW   (OFF_T5  + (size_t)NR_ * 160)
#define OFF_R    (OFF_XW  + NC_)      // R,K,V,G contiguous
#define OFF_K    (OFF_R   + NC_)
#define OFF_V    (OFF_K   + NC_)
#define OFF_G    (OFF_V   + NC_)
#define OFF_H1   (OFF_G   + NC_)
#define OFF_WDEC (OFF_H1  + (size_t)NR_ * 64)
#define OFF_Y    (OFF_WDEC+ NC_)
#define OFF_RUK  (OFF_Y   + NC_)

// ========================= helpers ==========================
__device__ __forceinline__ uint32_t smem_u32(const void* p) {
    uint32_t a;
    asm("{ .reg .u64 t; cvta.to.shared.u64 t, %1; cvt.u32.u64 %0, t; }" : "=r"(a) : "l"(p));
    return a;
}
__device__ __forceinline__ void ldsm_x4(uint32_t* r, uint32_t addr) {
    asm volatile("ldmatrix.sync.aligned.m8n8.x4.shared.b16 {%0,%1,%2,%3}, [%4];"
                 : "=r"(r[0]), "=r"(r[1]), "=r"(r[2]), "=r"(r[3]) : "r"(addr));
}
__device__ __forceinline__ void mma_bf16(float* c, const uint32_t* a, uint32_t b0, uint32_t b1) {
    asm volatile("mma.sync.aligned.m16n8k16.row.col.f32.bf16.bf16.f32 "
                 "{%0,%1,%2,%3}, {%4,%5,%6,%7}, {%8,%9}, {%0,%1,%2,%3};"
                 : "+f"(c[0]), "+f"(c[1]), "+f"(c[2]), "+f"(c[3])
                 : "r"(a[0]), "r"(a[1]), "r"(a[2]), "r"(a[3]), "r"(b0), "r"(b1));
}

// ==========================================================================
// bf16-split tensor-core GEMM body (M=128, N=768 full-tile version)
// ==========================================================================
#define PLANE_   2080
#define ATILE_   (4 * PLANE_)
#define BUFSZ_   (2 * ATILE_)

__device__ __forceinline__ void gemm_mma_body(
    const __nv_bfloat16* __restrict__ Ahi, const __nv_bfloat16* __restrict__ Alo,
    const __nv_bfloat16* __restrict__ Whi, const __nv_bfloat16* __restrict__ Wlo,
    float* __restrict__ Cmat, int doRelu, char* sm)
{
    const int tid  = threadIdx.x;
    const int warp = tid >> 5;
    const int lane = tid & 31;
    const int m0 = blockIdx.y * 128;
    const int n0 = blockIdx.x * 128;
    const int wm = warp >> 2;
    const int wn = warp & 3;

    float acc[4][4][4];
#pragma unroll
    for (int i = 0; i < 4; i++)
#pragma unroll
        for (int j = 0; j < 4; j++)
#pragma unroll
            for (int q = 0; q < 4; q++) acc[i][j][q] = 0.f;

    const int ldrow = tid >> 1;
    const int ldcb  = (tid & 1) * 2;

    uint4 ra[2], rb[2];

    const uint32_t sb = smem_u32(sm);
    const int lgrp = lane >> 3;
    const int lrl  = lane & 7;

#define LDG_T(c_)                                                               \
    {                                                                           \
        const int seg_ = (c_) / 24;                                             \
        const int kc_  = ((c_) % 24) * 32;                                      \
        const __nv_bfloat16* Ag = (seg_ == 1) ? Alo : Ahi;                      \
        const __nv_bfloat16* Bg = (seg_ == 2) ? Wlo : Whi;                      \
        const __nv_bfloat16* ap = Ag + (size_t)(m0 + ldrow) * C_ + kc_ + ldcb * 8; \
        const __nv_bfloat16* bp = Bg + (size_t)(n0 + ldrow) * C_ + kc_ + ldcb * 8; \
        ra[0] = *(const uint4*)ap; ra[1] = *(const uint4*)(ap + 8);             \
        rb[0] = *(const uint4*)bp; rb[1] = *(const uint4*)(bp + 8);             \
    }

#define STS_T(buf_)                                                             \
    {                                                                           \
        char* b_ = sm + (buf_) * BUFSZ_;                                        \
        *(uint4*)(b_ + (ldcb + 0) * PLANE_ + ldrow * 16) = ra[0];               \
        *(uint4*)(b_ + (ldcb + 1) * PLANE_ + ldrow * 16) = ra[1];               \
        *(uint4*)(b_ + ATILE_ + (ldcb + 0) * PLANE_ + ldrow * 16) = rb[0];      \
        *(uint4*)(b_ + ATILE_ + (ldcb + 1) * PLANE_ + ldrow * 16) = rb[1];      \
    }

    LDG_T(0);
    STS_T(0);
    __syncthreads();

    for (int c = 0; c < 72; c++) {
        const int buf = c & 1;
        const bool hasNext = (c + 1 < 72);
        if (hasNext) LDG_T(c + 1);

        const uint32_t abase = sb + buf * BUFSZ_;
        const uint32_t bbase = abase + ATILE_;

#pragma unroll
        for (int kk = 0; kk < 2; kk++) {
            uint32_t afr[4][4], bfr[2][4];
#pragma unroll
            for (int mt = 0; mt < 4; mt++) {
                int row   = wm * 64 + mt * 16 + (lgrp & 1) * 8 + lrl;
                int chunk = kk * 2 + (lgrp >> 1);
                ldsm_x4(afr[mt], abase + chunk * PLANE_ + row * 16);
            }
#pragma unroll
            for (int nt = 0; nt < 2; nt++) {
                int nr    = wn * 32 + nt * 16 + (lgrp >> 1) * 8 + lrl;
                int chunk = kk * 2 + (lgrp & 1);
                ldsm_x4(bfr[nt], bbase + chunk * PLANE_ + nr * 16);
            }
#pragma unroll
            for (int mt = 0; mt < 4; mt++)
#pragma unroll
                for (int ng = 0; ng < 4; ng++)
                    mma_bf16(acc[mt][ng], afr[mt], bfr[ng >> 1][(ng & 1) * 2 + 0],
                             bfr[ng >> 1][(ng & 1) * 2 + 1]);
        }

        if (hasNext) {
            STS_T(buf ^ 1);
            __syncthreads();
        }
    }
#undef LDG_T
#undef STS_T

#pragma unroll
    for (int mt = 0; mt < 4; mt++) {
        const int r0 = m0 + wm * 64 + mt * 16 + (lane >> 2);
#pragma unroll
        for (int ng = 0; ng < 4; ng++) {
            const int col = n0 + wn * 32 + ng * 8 + (lane & 3) * 2;
            float c0 = acc[mt][ng][0], c1 = acc[mt][ng][1];
            float c2 = acc[mt][ng][2], c3 = acc[mt][ng][3];
            if (doRelu) {
                c0 = fmaxf(c0, 0.f); c1 = fmaxf(c1, 0.f);
                c2 = fmaxf(c2, 0.f); c3 = fmaxf(c3, 0.f);
            }
            *(float2*)(Cmat + (size_t)r0 * C_ + col)       = make_float2(c0, c1);
            *(float2*)(Cmat + (size_t)(r0 + 8) * C_ + col) = make_float2(c2, c3);
        }
    }
}

// Batched r/k/v/g GEMMs: gridDim.z = 4 selects act slot / weight / output.
__global__ void __launch_bounds__(256, 2)
k_gemm_mma4(const __nv_bfloat16* __restrict__ acthi, const __nv_bfloat16* __restrict__ actlo,
            const __nv_bfloat16* __restrict__ w5hi, const __nv_bfloat16* __restrict__ w5lo,
            float* __restrict__ outbase)
{
    __shared__ __align__(16) char sm[2 * BUFSZ_];
    const int z = blockIdx.z;
    const int aslot = (z == 0) ? 2 : (z == 1) ? 0 : (z == 2) ? 1 : 3;
    gemm_mma_body(acthi + (size_t)aslot * NC_, actlo + (size_t)aslot * NC_,
                  w5hi + (size_t)z * WSZ_, w5lo + (size_t)z * WSZ_,
                  outbase + (size_t)z * NC_, z == 3, sm);
}

// Single GEMM (W_o path)
__global__ void __launch_bounds__(256, 2)
k_gemm_mma(const __nv_bfloat16* __restrict__ Ahi, const __nv_bfloat16* __restrict__ Alo,
           const __nv_bfloat16* __restrict__ Whi, const __nv_bfloat16* __restrict__ Wlo,
           float* __restrict__ Cmat, int doRelu)
{
    __shared__ __align__(16) char sm[2 * BUFSZ_];
    gemm_mma_body(Ahi, Alo, Whi, Wlo, Cmat, doRelu, sm);
}

// ==========================================================================
// t5 GEMM via mma, M-tile 64: t5[8192,160] = tanh( xxx @ maa_w1 )
// grid (2, 128), 256 thr, warp tile 32x32. A planes 64-row (stride 1056).
// ==========================================================================
#define APL5_   1056
#define ATL5_   (4 * APL5_)            // 4224
#define STG5_   (ATL5_ + 4 * PLANE_)   // 12544

__global__ void __launch_bounds__(256, 2)
k_gemm_mma_t5(const __nv_bfloat16* __restrict__ Ahi, const __nv_bfloat16* __restrict__ Alo,
              const __nv_bfloat16* __restrict__ Whi, const __nv_bfloat16* __restrict__ Wlo,
              float* __restrict__ out)
{
    __shared__ __align__(16) char sm[2 * STG5_];
    const int tid  = threadIdx.x;
    const int warp = tid >> 5;
    const int lane = tid & 31;
    const int m0 = blockIdx.y * 64;
    const int n0 = blockIdx.x * 128;
    const int wm = warp >> 2;      // 0..1 (32 rows each)
    const int wn = warp & 3;       // 0..3 (32 cols each)

    float acc[2][4][4];
#pragma unroll
    for (int i = 0; i < 2; i++)
#pragma unroll
        for (int j = 0; j < 4; j++)
#pragma unroll
            for (int q = 0; q < 4; q++) acc[i][j][q] = 0.f;

    const int arow = tid >> 2;     // 0..63
    const int ach  = tid & 3;      // 0..3
    const int brow = tid >> 1;     // 0..127
    const int bcb  = (tid & 1) * 2;
    const bool bok = (n0 + brow) < 160;
    const uint4 z4 = make_uint4(0u, 0u, 0u, 0u);

    uint4 ra, rb[2];
    const uint32_t sb = smem_u32(sm);
    const int lgrp = lane >> 3;
    const int lrl  = lane & 7;

#define LDG_T5(c_)                                                              \
    {                                                                           \
        const int seg_ = (c_) / 24;                                             \
        const int kc_  = ((c_) % 24) * 32;                                      \
        const __nv_bfloat16* Ag = (seg_ == 1) ? Alo : Ahi;                      \
        const __nv_bfloat16* Bg = (seg_ == 2) ? Wlo : Whi;                      \
        ra = *(const uint4*)(Ag + (size_t)(m0 + arow) * C_ + kc_ + ach * 8);    \
        if (bok) {                                                              \
            const __nv_bfloat16* bp = Bg + (size_t)(n0 + brow) * C_ + kc_ + bcb * 8; \
            rb[0] = *(const uint4*)bp; rb[1] = *(const uint4*)(bp + 8);         \
        } else { rb[0] = z4; rb[1] = z4; }                                      \
    }

#define STS_T5(buf_)                                                            \
    {                                                                           \
        char* b_ = sm + (buf_) * STG5_;                                         \
        *(uint4*)(b_ + ach * APL5_ + arow * 16) = ra;                           \
        *(uint4*)(b_ + ATL5_ + (bcb + 0) * PLANE_ + brow * 16) = rb[0];         \
        *(uint4*)(b_ + ATL5_ + (bcb + 1) * PLANE_ + brow * 16) = rb[1];         \
    }

    LDG_T5(0);
    STS_T5(0);
    __syncthreads();

    for (int c = 0; c < 72; c++) {
        const int buf = c & 1;
        const bool hasNext = (c + 1 < 72);
        if (hasNext) LDG_T5(c + 1);

        const uint32_t abase = sb + buf * STG5_;
        const uint32_t bbase = abase + ATL5_;

#pragma unroll
        for (int kk = 0; kk < 2; kk++) {
            uint32_t afr[2][4], bfr[2][4];
#pragma unroll
            for (int mt = 0; mt < 2; mt++) {
                int row   = wm * 32 + mt * 16 + (lgrp & 1) * 8 + lrl;
                int chunk = kk * 2 + (lgrp >> 1);
                ldsm_x4(afr[mt], abase + chunk * APL5_ + row * 16);
            }
#pragma unroll
            for (int nt = 0; nt < 2; nt++) {
                int nr    = wn * 32 + nt * 16 + (lgrp >> 1) * 8 + lrl;
                int chunk = kk * 2 + (lgrp & 1);
                ldsm_x4(bfr[nt], bbase + chunk * PLANE_ + nr * 16);
            }
#pragma unroll
            for (int mt = 0; mt < 2; mt++)
#pragma unroll
                for (int ng = 0; ng < 4; ng++)
                    mma_bf16(acc[mt][ng], afr[mt], bfr[ng >> 1][(ng & 1) * 2 + 0],
                             bfr[ng >> 1][(ng & 1) * 2 + 1]);
        }

        if (hasNext) {
            STS_T5(buf ^ 1);
            __syncthreads();
        }
    }
#undef LDG_T5
#undef STS_T5

#pragma unroll
    for (int mt = 0; mt < 2; mt++) {
        const int r0 = m0 + wm * 32 + mt * 16 + (lane >> 2);
#pragma unroll
        for (int ng = 0; ng < 4; ng++) {
            const int col = n0 + wn * 32 + ng * 8 + (lane & 3) * 2;
            if (col < 160) {
                float c0 = tanhf(acc[mt][ng][0]), c1 = tanhf(acc[mt][ng][1]);
                float c2 = tanhf(acc[mt][ng][2]), c3 = tanhf(acc[mt][ng][3]);
                *(float2*)(out + (size_t)r0 * 160 + col)       = make_float2(c0, c1);
                *(float2*)(out + (size_t)(r0 + 8) * 160 + col) = make_float2(c2, c3);
            }
        }
    }
}

// ==========================================================================
// Fused decay: per 64-row block, h1 = tanh(xw @ dec_w1) in smem, then
// wdec = exp(-exp(tdec + h1 @ dec_w2)). fp32 throughout. grid 128 blocks.
// ==========================================================================
__global__ void __launch_bounds__(256, 2)
k_decay(const float* __restrict__ xw, const float* __restrict__ w1,
        const float* __restrict__ w2, const float* __restrict__ tdec,
        float* __restrict__ wdec)
{
    const int r0  = blockIdx.x * 64;
    const int tid = threadIdx.x;
    const int tm  = (tid >> 4) * 4;   // 0..60
    const int tn  = (tid & 15) * 4;   // 0..60

    __shared__ float h1s[64][65];
    __shared__ __align__(16) float smbuf[64][68];   // stage1: As=rows0-31, Bs=rows32-63; stage2: Ws

    // ---- stage 1: h1[64][64] = tanh(xw @ w1), K = 768 ----
    float acc[4][4];
#pragma unroll
    for (int i = 0; i < 4; i++)
#pragma unroll
        for (int j = 0; j < 4; j++) acc[i][j] = 0.f;

    for (int k0 = 0; k0 < C_; k0 += 32) {
#pragma unroll
        for (int l = 0; l < 2; l++) {
            int e = tid + l * 256;            // 0..511
            int row = e >> 3;                 // 0..63
            int kk4 = (e & 7) * 4;            // 0..28
            float4 a4 = *(const float4*)(xw + (size_t)(r0 + row) * C_ + k0 + kk4);
            smbuf[kk4 + 0][row] = a4.x; smbuf[kk4 + 1][row] = a4.y;
            smbuf[kk4 + 2][row] = a4.z; smbuf[kk4 + 3][row] = a4.w;
        }
#pragma unroll
        for (int l = 0; l < 2; l++) {
            int e = tid + l * 256;
            int kk = e >> 4;                  // 0..31
            int cc = (e & 15) * 4;
            *(float4*)(&smbuf[32 + kk][cc]) = *(const float4*)(w1 + (size_t)(k0 + kk) * 64 + cc);
        }
        __syncthreads();

#pragma unroll
        for (int kk = 0; kk < 32; kk++) {
            float4 a4 = *(const float4*)(&smbuf[kk][tm]);
            float4 b4 = *(const float4*)(&smbuf[32 + kk][tn]);
            acc[0][0] = fmaf(a4.x, b4.x, acc[0][0]); acc[0][1] = fmaf(a4.x, b4.y, acc[0][1]);
            acc[0][2] = fmaf(a4.x, b4.z, acc[0][2]); acc[0][3] = fmaf(a4.x, b4.w, acc[0][3]);
            acc[1][0] = fmaf(a4.y, b4.x, acc[1][0]); acc[1][1] = fmaf(a4.y, b4.y, acc[1][1]);
            acc[1][2] = fmaf(a4.y, b4.z, acc[1][2]); acc[1][3] = fmaf(a4.y, b4.w, acc[1][3]);
            acc[2][0] = fmaf(a4.z, b4.x, acc[2][0]); acc[2][1] = fmaf(a4.z, b4.y, acc[2][1]);
            acc[2][2] = fmaf(a4.z, b4.z, acc[2][2]); acc[2][3] = fmaf(a4.z, b4.w, acc[2][3]);
            acc[3][0] = fmaf(a4.w, b4.x, acc[3][0]); acc[3][1] = fmaf(a4.w, b4.y, acc[3][1]);
            acc[3][2] = fmaf(a4.w, b4.z, acc[3][2]); acc[3][3] = fmaf(a4.w, b4.w, acc[3][3]);
        }
        __syncthreads();
    }
#pragma unroll
    for (int i = 0; i < 4; i++)
#pragma unroll
        for (int j = 0; j < 4; j++)
            h1s[tm + i][tn + j] = tanhf(acc[i][j]);
    __syncthreads();

    // ---- stage 2: wdec[64][768] = exp(-exp(tdec + h1 @ w2)), K = 64 ----
    for (int nc = 0; nc < 12; nc++) {
        const int nb = nc * 64;
#pragma unroll
        for (int l = 0; l < 2; l++) {
            int e = tid + l * 256;
            int kk = e >> 4;
            int cc = (e & 15) * 4;
            *(float4*)(&smbuf[kk][cc]) = *(const float4*)(w2 + (size_t)kk * C_ + nb + cc);
        }
        __syncthreads();

        float a2[4][4];
#pragma unroll
        for (int i = 0; i < 4; i++)
#pragma unroll
            for (int j = 0; j < 4; j++) a2[i][j] = 0.f;

#pragma unroll
        for (int kk = 0; kk < 64; kk++) {
            float4 b4 = *(const float4*)(&smbuf[kk][tn]);
            float a0 = h1s[tm + 0][kk], a1 = h1s[tm + 1][kk];
            float a22 = h1s[tm + 2][kk], a3 = h1s[tm + 3][kk];
            a2[0][0] = fmaf(a0, b4.x, a2[0][0]); a2[0][1] = fmaf(a0, b4.y, a2[0][1]);
            a2[0][2] = fmaf(a0, b4.z, a2[0][2]); a2[0][3] = fmaf(a0, b4.w, a2[0][3]);
            a2[1][0] = fmaf(a1, b4.x, a2[1][0]); a2[1][1] = fmaf(a1, b4.y, a2[1][1]);
            a2[1][2] = fmaf(a1, b4.z, a2[1][2]); a2[1][3] = fmaf(a1, b4.w, a2[1][3]);
            a2[2][0] = fmaf(a22, b4.x, a2[2][0]); a2[2][1] = fmaf(a22, b4.y, a2[2][1]);
            a2[2][2] = fmaf(a22, b4.z, a2[2][2]); a2[2][3] = fmaf(a22, b4.w, a2[2][3]);
            a2[3][0] = fmaf(a3, b4.x, a2[3][0]); a2[3][1] = fmaf(a3, b4.y, a2[3][1]);
            a2[3][2] = fmaf(a3, b4.z, a2[3][2]); a2[3][3] = fmaf(a3, b4.w, a2[3][3]);
        }

        float4 td = *(const float4*)(tdec + nb + tn);
#pragma unroll
        for (int i = 0; i < 4; i++) {
            float4 o;
            o.x = expf(-expf(td.x + a2[i][0]));
            o.y = expf(-expf(td.y + a2[i][1]));
            o.z = expf(-expf(td.z + a2[i][2]));
            o.w = expf(-expf(td.w + a2[i][3]));
            *(float4*)(wdec + (size_t)(r0 + tm + i) * C_ + nb + tn) = o;
        }
        __syncthreads();
    }
}

// ==========================================================================
// Split all five weight matrices into bf16 hi/lo once (float4 vectorized).
// ==========================================================================
__global__ void __launch_bounds__(256)
k_split5(const float* __restrict__ w0, const float* __restrict__ w1,
         const float* __restrict__ w2, const float* __restrict__ w3,
         const float* __restrict__ w4,
         __nv_bfloat16* __restrict__ hi, __nv_bfloat16* __restrict__ lo)
{
    size_t i4 = (size_t)blockIdx.x * blockDim.x + threadIdx.x;
    size_t idx = i4 * 4;
    int sel = (int)(idx / WSZ_);
    size_t off = idx % WSZ_;
    const float* src = (sel == 0) ? w0 : (sel == 1) ? w1 : (sel == 2) ? w2 : (sel == 3) ? w3 : w4;
    float4 a = *(const float4*)(src + off);
    __nv_bfloat16 h0 = __float2bfloat16(a.x);
    __nv_bfloat16 h1 = __float2bfloat16(a.y);
    __nv_bfloat16 h2 = __float2bfloat16(a.z);
    __nv_bfloat16 h3 = __float2bfloat16(a.w);
    __nv_bfloat162 hp0, hp1, lp0, lp1;
    hp0.x = h0; hp0.y = h1; hp1.x = h2; hp1.y = h3;
    lp0.x = __float2bfloat16(a.x - __bfloat162float(h0));
    lp0.y = __float2bfloat16(a.y - __bfloat162float(h1));
    lp1.x = __float2bfloat16(a.z - __bfloat162float(h2));
    lp1.y = __float2bfloat16(a.w - __bfloat162float(h3));
    *(uint2*)(hi + idx) = make_uint2(*(uint32_t*)&hp0, *(uint32_t*)&hp1);
    *(uint2*)(lo + idx) = make_uint2(*(uint32_t*)&lp0, *(uint32_t*)&lp1);
}

// ==========================================================================
// Transpose + split maa_w1 [768,160] -> w1t hi/lo [160,768]
// ==========================================================================
__global__ void __launch_bounds__(256)
k_splitw1t(const float* __restrict__ w1,
           __nv_bfloat16* __restrict__ hi, __nv_bfloat16* __restrict__ lo)
{
    int idx = blockIdx.x * 256 + threadIdx.x;   // < 160*768
    int n  = idx / C_;
    int kk = idx % C_;
    float a = w1[(size_t)kk * 160 + n];
    __nv_bfloat16 h = __float2bfloat16(a);
    hi[idx] = h;
    lo[idx] = __float2bfloat16(a - __bfloat162float(h));
}

// ==========================================================================
// q-shift (float4) -> xx fp32 ; xxx emitted as bf16 hi/lo
// ==========================================================================
__global__ void __launch_bounds__(256)
k_shift(const float* __restrict__ x, const float* __restrict__ maa_x,
        float* __restrict__ xx,
        __nv_bfloat16* __restrict__ xhi, __nv_bfloat16* __restrict__ xlo)
{
    size_t i4 = (size_t)blockIdx.x * blockDim.x + threadIdx.x;
    size_t idx = i4 * 4;
    int c  = (int)(idx % C_);
    int bt = (int)(idx / C_);
    int t  = bt % T_;
    int w  = t % PW_;
    int h  = t / PW_;
    int quarter = (c & (HS_ - 1)) >> 4;

    float4 src = make_float4(0.f, 0.f, 0.f, 0.f);
    if (quarter == 0)      { if (w > 0)       src = *(const float4*)(x + idx - C_); }
    else if (quarter == 1) { if (w < PW_ - 1) src = *(const float4*)(x + idx + C_); }
    else if (quarter == 2) { if (h > 0)       src = *(const float4*)(x + idx - PW_ * C_); }
    else                   { if (h < PH_ - 1) src = *(const float4*)(x + idx + PW_ * C_); }

    float4 xv = *(const float4*)(x + idx);
    float4 mv = *(const float4*)(maa_x + c);
    float4 d, o;
    d.x = src.x - xv.x; d.y = src.y - xv.y; d.z = src.z - xv.z; d.w = src.w - xv.w;
    o.x = fmaf(d.x, mv.x, xv.x); o.y = fmaf(d.y, mv.y, xv.y);
    o.z = fmaf(d.z, mv.z, xv.z); o.w = fmaf(d.w, mv.w, xv.w);
    *(float4*)(xx + idx) = d;

    __nv_bfloat162 hp0, hp1, lp0, lp1;
    hp0.x = __float2bfloat16(o.x); hp0.y = __float2bfloat16(o.y);
    hp1.x = __float2bfloat16(o.z); hp1.y = __float2bfloat16(o.w);
    lp0.x = __float2bfloat16(o.x - __bfloat162float(hp0.x));
    lp0.y = __float2bfloat16(o.y - __bfloat162float(hp0.y));
    lp1.x = __float2bfloat16(o.z - __bfloat162float(hp1.x));
    lp1.y = __float2bfloat16(o.w - __bfloat162float(hp1.y));
    *(uint2*)(xhi + idx) = make_uint2(*(uint32_t*)&hp0, *(uint32_t*)&hp1);
    *(uint2*)(xlo + idx) = make_uint2(*(uint32_t*)&lp0, *(uint32_t*)&lp1);
}

// ==========================================================================
// Fused token-mix v4 (unchanged winner)
// ==========================================================================
__global__ void __launch_bounds__(256, 2)
k_mix(const float* __restrict__ x, const float* __restrict__ xx,
      const float* __restrict__ t5, const float* __restrict__ w2,
      const float* __restrict__ ma0, const float* __restrict__ ma1,
      const float* __restrict__ ma2, const float* __restrict__ ma3,
      const float* __restrict__ ma4,
      float* __restrict__ xw,
      __nv_bfloat16* __restrict__ acthi, __nv_bfloat16* __restrict__ actlo)
{
    const int r0  = blockIdx.x * 64;
    const int c0  = blockIdx.y * 128;
    const int tid = threadIdx.x;
    const int cp  = (tid & 63) * 2;
    const int rh  = tid >> 6;

    __shared__ __align__(16) float tsh[64][36];

    float2 mfv[5];
    mfv[0] = *(const float2*)(ma0 + c0 + cp);
    mfv[1] = *(const float2*)(ma1 + c0 + cp);
    mfv[2] = *(const float2*)(ma2 + c0 + cp);
    mfv[3] = *(const float2*)(ma3 + c0 + cp);
    mfv[4] = *(const float2*)(ma4 + c0 + cp);

    for (int f = 0; f < 5; f++) {
#pragma unroll
        for (int l = 0; l < 8; l++) {
            int e = tid + l * 256;
            tsh[e >> 5][e & 31] = t5[(size_t)(r0 + (e >> 5)) * 160 + f * 32 + (e & 31)];
        }
        float2 wreg[32];
#pragma unroll
        for (int rr = 0; rr < 32; rr++)
            wreg[rr] = *(const float2*)(w2 + (size_t)(f * 32 + rr) * C_ + c0 + cp);
        __syncthreads();

        const float2 mf = mfv[f];
        const size_t slotoff = (size_t)(f - 1) * NC_;
        size_t idx = (size_t)(r0 + rh) * C_ + c0 + cp;

#pragma unroll 4
        for (int it = 0; it < 16; it++) {
            const int row = rh + it * 4;
            float2 xv  = *(const float2*)(x + idx);
            float2 xxv = *(const float2*)(xx + idx);
            const float4* trow = (const float4*)(&tsh[row][0]);
            float a0 = 0.f, a1 = 0.f;
#pragma unroll
            for (int q = 0; q < 8; q++) {
                float4 t4 = trow[q];
                float2 w0 = wreg[4 * q + 0], w1 = wreg[4 * q + 1];
                float2 w2r = wreg[4 * q + 2], w3 = wreg[4 * q + 3];
                a0 = fmaf(t4.x, w0.x, a0); a1 = fmaf(t4.x, w0.y, a1);
                a0 = fmaf(t4.y, w1.x, a0); a1 = fmaf(t4.y, w1.y, a1);
                a0 = fmaf(t4.z, w2r.x, a0); a1 = fmaf(t4.z, w2r.y, a1);
                a0 = fmaf(t4.w, w3.x, a0); a1 = fmaf(t4.w, w3.y, a1);
            }
            float v0 = fmaf(xxv.x, mf.x + a0, xv.x);
            float v1 = fmaf(xxv.y, mf.y + a1, xv.y);
            if (f == 0) {
                *(float2*)(xw + idx) = make_float2(v0, v1);
            } else {
                __nv_bfloat162 hp, lp;
                hp.x = __float2bfloat16(v0);
                hp.y = __float2bfloat16(v1);
                lp.x = __float2bfloat16(v0 - __bfloat162float(hp.x));
                lp.y = __float2bfloat16(v1 - __bfloat162float(hp.y));
                *(uint32_t*)(acthi + slotoff + idx) = *(uint32_t*)&hp;
                *(uint32_t*)(actlo + slotoff + idx) = *(uint32_t*)&lp;
            }
            idx += 4 * C_;
        }
        __syncthreads();
    }
}

// ==========================================================================
// ruk[row,h] = sum_j r*u*k
// ==========================================================================
__global__ void k_ruk(const float* __restrict__ r, const float* __restrict__ k,
                      const float* __restrict__ u, float* __restrict__ ruk)
{
    const int row = blockIdx.x;
    const int c   = threadIdx.x;
    const int h   = c >> 6;
    const int j   = c & 63;
    size_t idx = (size_t)row * C_ + c;
    float p = r[idx] * u[c] * k[idx];
#pragma unroll
    for (int off = 16; off; off >>= 1) p += __shfl_xor_sync(0xffffffffu, p, off);
    __shared__ float ws[24];
    if ((c & 31) == 0) ws[c >> 5] = p;
    __syncthreads();
    if (j == 0) ruk[(size_t)row * H_ + h] = ws[2 * h] + ws[2 * h + 1];
}

// ==========================================================================
// WKV6 recurrence (R11 proven version)
// ==========================================================================
__global__ void __launch_bounds__(256)
k_wkv(const float* __restrict__ r, const float* __restrict__ k,
      const float* __restrict__ v, const float* __restrict__ wd,
      const float* __restrict__ ruk, float* __restrict__ y)
{
    const int bh = blockIdx.x;
    const int b  = bh / H_;
    const int h  = bh % H_;
    const int tid = threadIdx.x;
    const int i  = tid & 63;
    const int q  = tid >> 6;

    __shared__ __align__(16) float sr[64];
    __shared__ __align__(16) float sk[64];
    __shared__ __align__(16) float sw[64];
    __shared__ __align__(16) float sv[64];
    __shared__ float part[3][64];

    float S[16];
#pragma unroll
    for (int jj = 0; jj < 16; jj++) S[jj] = 0.f;

    const size_t base  = (size_t)b * T_ * C_ + h * 64;
    const size_t rbase = (size_t)b * T_ * H_ + h;

    const float* mysrc = (q == 0) ? r : (q == 1) ? k : (q == 2) ? wd : v;
    float cur = mysrc[base + i];

    for (int t = 0; t < T_; t++) {
        if (q == 0)      sr[i] = cur;
        else if (q == 1) sk[i] = cur;
        else if (q == 2) sw[i] = cur;
        else             sv[i] = cur;
        __syncthreads();

        float nxt = cur;
        if (t + 1 < T_) nxt = mysrc[base + (size_t)(t + 1) * C_ + i];

        const float vi = sv[i];
        float yp = 0.f;
#pragma unroll
        for (int g4 = 0; g4 < 4; g4++) {
            float4 r4 = *(const float4*)(sr + q * 16 + g4 * 4);
            float4 k4 = *(const float4*)(sk + q * 16 + g4 * 4);
            float4 w4 = *(const float4*)(sw + q * 16 + g4 * 4);
            float kv;
            kv = k4.x * vi; yp = fmaf(r4.x, S[4*g4+0], yp); S[4*g4+0] = fmaf(w4.x, S[4*g4+0], kv);
            kv = k4.y * vi; yp = fmaf(r4.y, S[4*g4+1], yp); S[4*g4+1] = fmaf(w4.y, S[4*g4+1], kv);
            kv = k4.z * vi; yp = fmaf(r4.z, S[4*g4+2], yp); S[4*g4+2] = fmaf(w4.z, S[4*g4+2], kv);
            kv = k4.w * vi; yp = fmaf(r4.w, S[4*g4+3], yp); S[4*g4+3] = fmaf(w4.w, S[4*g4+3], kv);
        }
        if (q) part[q - 1][i] = yp;
        __syncthreads();

        if (q == 0) {
            float yv = yp + part[0][i] + part[1][i] + part[2][i];
            yv = fmaf(ruk[rbase + (size_t)t * H_], vi, yv);
            y[base + (size_t)t * C_ + i] = yv;
        }
        cur = nxt;
    }
}

// ==========================================================================
// GroupNorm * g -> bf16 hi/lo split directly (for the W_o GEMM)
// ==========================================================================
__global__ void k_gnorm(const float* __restrict__ y, const float* __restrict__ gbuf,
                        const float* __restrict__ lnw, const float* __restrict__ lnb,
                        __nv_bfloat16* __restrict__ hi, __nv_bfloat16* __restrict__ lo)
{
    const int row = blockIdx.x;
    const int c   = threadIdx.x;
    size_t idx = (size_t)row * C_ + c;
    float v = y[idx];
    float s = v, s2 = v * v;
#pragma unroll
    for (int off = 16; off; off >>= 1) {
        s  += __shfl_xor_sync(0xffffffffu, s,  off);
        s2 += __shfl_xor_sync(0xffffffffu, s2, off);
    }
    __shared__ float as[24], as2[24];
    if ((c & 31) == 0) { as[c >> 5] = s; as2[c >> 5] = s2; }
    __syncthreads();
    const int g = c >> 6;
    float sum  = as[2 * g]  + as[2 * g + 1];
    float sum2 = as2[2 * g] + as2[2 * g + 1];
    float mu   = sum * (1.f / 64.f);
    float var  = sum2 * (1.f / 64.f) - mu * mu;
    float nv   = (v - mu) * rsqrtf(var + 1e-5f);
    float val  = fmaf(nv, lnw[c], lnb[c]) * gbuf[idx];
    __nv_bfloat16 h = __float2bfloat16(val);
    hi[idx] = h;
    lo[idx] = __float2bfloat16(val - __bfloat162float(h));
}

// ==========================================================================
// Host launcher
// ==========================================================================
extern "C" void kernel_launch(void* const* d_in, const int* in_sizes, int n_in,
                              void* d_out, int out_size)
{
    const float* x     = (const float*)d_in[0];
    const float* W_r   = (const float*)d_in[1];
    const float* W_k   = (const float*)d_in[2];
    const float* W_v   = (const float*)d_in[3];
    const float* W_g   = (const float*)d_in[4];
    const float* W_o   = (const float*)d_in[5];
    const float* maa_x = (const float*)d_in[6];
    const float* maa_w = (const float*)d_in[7];
    const float* maa_k = (const float*)d_in[8];
    const float* maa_v = (const float*)d_in[9];
    const float* maa_r = (const float*)d_in[10];
    const float* maa_g = (const float*)d_in[11];
    const float* maa_w1= (const float*)d_in[12];
    const float* maa_w2= (const float*)d_in[13];
    const float* tdec  = (const float*)d_in[14];
    const float* dec_w1= (const float*)d_in[15];
    const float* dec_w2= (const float*)d_in[16];
    const float* faaaa = (const float*)d_in[17];
    const float* ln_w  = (const float*)d_in[18];
    const float* ln_b  = (const float*)d_in[19];
    (void)in_sizes; (void)n_in; (void)out_size;

    float* S = nullptr;
    cudaGetSymbolAddress((void**)&S, g_scratch);
    __nv_bfloat16 *acthi = nullptr, *actlo = nullptr, *w5hi = nullptr, *w5lo = nullptr;
    __nv_bfloat16 *w1thi = nullptr, *w1tlo = nullptr;
    cudaGetSymbolAddress((void**)&acthi, g_acthi);
    cudaGetSymbolAddress((void**)&actlo, g_actlo);
    cudaGetSymbolAddress((void**)&w5hi, g_w5hi);
    cudaGetSymbolAddress((void**)&w5lo, g_w5lo);
    cudaGetSymbolAddress((void**)&w1thi, g_w1thi);
    cudaGetSymbolAddress((void**)&w1tlo, g_w1tlo);

    float* xx   = S + OFF_XX;
    float* t5   = S + OFF_T5;
    float* xw   = S + OFF_XW;
    float* rb   = S + OFF_R;
    float* kb   = S + OFF_K;
    float* vb   = S + OFF_V;
    float* wdec = S + OFF_WDEC;
    float* yb   = S + OFF_Y;
    float* ruk  = S + OFF_RUK;
    float* outp = (float*)d_out;

    // 0. split all 5 weights + transpose-split maa_w1
    k_split5<<<(unsigned)(5 * WSZ_ / 4 / 256), 256>>>(W_r, W_k, W_v, W_g, W_o, w5hi, w5lo);
    k_splitw1t<<<(160 * C_) / 256, 256>>>(maa_w1, w1thi, w1tlo);

    // 1. shift: xx fp32 + xxx bf16 hi/lo (into act slot 0; consumed before k_mix)
    k_shift<<<(unsigned)(NC_ / 4 / 256), 256>>>(x, maa_x, xx, acthi, actlo);

    // 2. t5 = tanh(xxx @ maa_w1)  (M64-tile mma, 256 blocks)
    k_gemm_mma_t5<<<dim3(2, NR_ / 64), 256>>>(acthi, actlo, w1thi, w1tlo, t5);

    // 3. fused token mix -> xw fp32 + bf16 hi/lo for k,v,r,g
    k_mix<<<dim3(NR_ / 64, C_ / 128), 256>>>(x, xx, t5, maa_w2,
                                             maa_w, maa_k, maa_v, maa_r, maa_g,
                                             xw, acthi, actlo);

    // 4. batched r/k/v/g GEMMs in ONE launch -> rb,kb,vb,gb
    k_gemm_mma4<<<dim3(C_ / 128, NR_ / 128, 4), 256>>>(acthi, actlo, w5hi, w5lo, rb);

    // 5. fused decay path (fp32): wdec = exp(-exp(tdec + tanh(xw@dec_w1)@dec_w2))
    k_decay<<<NR_ / 64, 256>>>(xw, dec_w1, dec_w2, tdec, wdec);

    // 6. wkv recurrence
    k_ruk<<<NR_, C_>>>(rb, kb, faaaa, ruk);
    k_wkv<<<B_ * H_, 256>>>(rb, kb, vb, wdec, ruk, yb);

    // 7. groupnorm * g -> bf16 pair (reuse act slot 0; gb = rb + 3*NC_)
    k_gnorm<<<NR_, C_>>>(yb, rb + 3 * NC_, ln_w, ln_b, acthi, actlo);

    // 8. out = yn @ W_o^T
    k_gemm_mma<<<dim3(C_ / 128, NR_ / 128), 256>>>(acthi, actlo,
                                                   w5hi + 4 * WSZ_, w5lo + 4 * WSZ_, outp, 0);
}